// round 15
// baseline (speedup 1.0000x reference)
#include <cuda_runtime.h>
#include <cuda_bf16.h>
#include <cstdint>
#include <cstddef>

#define Dm 1024
#define FFNm 4096
#define SEGm 128
#define LLm 256
#define MMm 4
#define BBm 64
#define UUm 128
#define RRm 32
#define TTm 160
#define QQm 161
#define KKm 420
#define BD (BBm*Dm)
#define NEG_INF_F (-1e8f)
#define EPS_LN 1e-5f
#define S0_OFF 0u
#define S1_OFF 8388608u
#define S2_OFF 10485760u
#define S3_OFF 10551296u
#define S4_OFF 10813440u
#define S5_OFF 27590656u

typedef __nv_bfloat16 bf16;
typedef __nv_bfloat162 bf162;

__device__ float g_cat[165*BD];
__device__ float g_res[TTm*BD];
__device__ float g_ff2[TTm*BD];
__device__ float g_ff2b[TTm*BD];
__device__ float g_scores[(size_t)1024*192*448];
__device__ bf16 g_ph[(size_t)1024*192*448], g_pl[(size_t)1024*192*448];
__device__ bf16 g_cat_h[165*BD], g_cat_l[165*BD];
__device__ bf16 g_qh[QQm*BD], g_ql[QQm*BD];
__device__ bf16 g_kh[448*BD], g_kl[448*BD];
__device__ bf16 g_vh[448*BD], g_vl[448*BD];
__device__ bf16 g_ah[QQm*BD], g_al[QQm*BD];
__device__ bf16 g_ffin_h[TTm*BD], g_ffin_l[TTm*BD];
__device__ bf16 g_ffh_h[(size_t)TTm*BBm*FFNm], g_ffh_l[(size_t)TTm*BBm*FFNm];
__device__ bf16 g_wq_h[Dm*Dm], g_wq_l[Dm*Dm];
__device__ bf16 g_wkv_h[2*Dm*Dm], g_wkv_l[2*Dm*Dm];
__device__ bf16 g_wo_h[Dm*Dm], g_wo_l[Dm*Dm];
__device__ bf16 g_w1_h[FFNm*Dm], g_w1_l[FFNm*Dm];
__device__ bf16 g_w2_h[Dm*FFNm], g_w2_l[Dm*FFNm];

__device__ __forceinline__ uint32_t smem_u32(const void* p){
    uint32_t a; asm("{ .reg .u64 t; cvta.to.shared.u64 t, %1; cvt.u32.u64 %0, t; }":"=r"(a):"l"(p)); return a;
}
__device__ __forceinline__ void cp16(uint32_t dst, const void* src){
    asm volatile("cp.async.cg.shared.global [%0], [%1], 16;"::"r"(dst),"l"(src));
}
__device__ __forceinline__ void ldsm4(uint32_t* r, uint32_t addr){
    asm volatile("ldmatrix.sync.aligned.m8n8.x4.shared.b16 {%0,%1,%2,%3}, [%4];"
        :"=r"(r[0]),"=r"(r[1]),"=r"(r[2]),"=r"(r[3]):"r"(addr));
}
__device__ __forceinline__ void ldsm4t(uint32_t* r, uint32_t addr){
    asm volatile("ldmatrix.sync.aligned.m8n8.x4.trans.shared.b16 {%0,%1,%2,%3}, [%4];"
        :"=r"(r[0]),"=r"(r[1]),"=r"(r[2]),"=r"(r[3]):"r"(addr));
}
__device__ __forceinline__ void mma16816(float* c, const uint32_t* a, uint32_t b0, uint32_t b1){
    asm volatile("mma.sync.aligned.m16n8k16.row.col.f32.bf16.bf16.f32 "
        "{%0,%1,%2,%3}, {%4,%5,%6,%7}, {%8,%9}, {%0,%1,%2,%3};"
        :"+f"(c[0]),"+f"(c[1]),"+f"(c[2]),"+f"(c[3])
        :"r"(a[0]),"r"(a[1]),"r"(a[2]),"r"(a[3]),"r"(b0),"r"(b1));
}
__device__ __forceinline__ void split_pack(float a, float b, uint32_t& hi, uint32_t& lo){
    bf16 ha=__float2bfloat16(a), hb=__float2bfloat16(b);
    hi=(uint32_t)__bfloat16_as_ushort(ha)|((uint32_t)__bfloat16_as_ushort(hb)<<16);
    bf16 la=__float2bfloat16(a-__bfloat162float(ha)), lb=__float2bfloat16(b-__bfloat162float(hb));
    lo=(uint32_t)__bfloat16_as_ushort(la)|((uint32_t)__bfloat16_as_ushort(lb)<<16);
}

// ---- HMMA split-bf16 GEMM body (tile 128x128, BK=32, fused 3-pass, 2-stage) ----
#define ROWB 80
#define TILEB 10240
#define STAGEB 40960
#define GEMM_SMEM (2*STAGEB)
__device__ __noinline__ void gemm_body(
    int bx, int by, int bz,
    const bf16* Ah_, const bf16* Al_, int lda,
    const bf16* Bh_, const bf16* Bl_, int ldb,
    const float* bias, int M, int K, int mode,
    float* F0, bf16* H0, bf16* L0, int ldc,
    bf16* H1, bf16* L1,
    float* F1, float* F2, float* F3)
{
    extern __shared__ __align__(16) char smem[];
    const int tid=threadIdx.x, wid=tid>>5, lane=tid&31;
    const int m0=by*128, n0=bx*128;
    const int m0w=(wid>>1)*32, n0w=(wid&1)*64;
    const uint32_t sb=smem_u32(smem);
    const int nIt=K>>5;
    const int kbase=bz*K;
    Ah_+=kbase; Al_+=kbase; Bh_+=kbase; Bl_+=kbase;
    if(bz==1){ F0=F3; bias=nullptr; }

    float acc[2][8][4];
#pragma unroll
    for(int i=0;i<2;i++)
#pragma unroll
        for(int j=0;j<8;j++)
#pragma unroll
            for(int l=0;l<4;l++) acc[i][j][l]=0.f;

    const int lrow=tid>>1, le0=(tid&1)*16;
    int gra=m0+lrow; if(gra>=M) gra=M-1;
    const int grb=n0+lrow;

    auto load_stage=[&](int it){
        int kk=it<<5;
        uint32_t st=sb+(it&1)*STAGEB;
        uint32_t rb=st+(uint32_t)lrow*ROWB+le0*2;
        cp16(rb,          Ah_+(size_t)gra*lda+kk+le0);
        cp16(rb+16,       Ah_+(size_t)gra*lda+kk+le0+8);
        cp16(rb+TILEB,    Al_+(size_t)gra*lda+kk+le0);
        cp16(rb+TILEB+16, Al_+(size_t)gra*lda+kk+le0+8);
        cp16(rb+2*TILEB,    Bh_+(size_t)grb*ldb+kk+le0);
        cp16(rb+2*TILEB+16, Bh_+(size_t)grb*ldb+kk+le0+8);
        cp16(rb+3*TILEB,    Bl_+(size_t)grb*ldb+kk+le0);
        cp16(rb+3*TILEB+16, Bl_+(size_t)grb*ldb+kk+le0+8);
        asm volatile("cp.async.commit_group;":::"memory");
    };

    load_stage(0); load_stage(1);
    for(int it=0; it<nIt; ++it){
        asm volatile("cp.async.wait_group 1;":::"memory");
        __syncthreads();
        uint32_t st=sb+(it&1)*STAGEB;
        uint32_t aoff=st+(uint32_t)(m0w+(lane&15))*ROWB+((lane>>4)<<4);
        uint32_t boff=st+2*TILEB+(uint32_t)(n0w+(lane&7)+((lane>>4)<<3))*ROWB+(((lane>>3)&1)<<4);
#pragma unroll
        for(int ks=0;ks<2;++ks){
            uint32_t af[4][4], bb[4][4];
            ldsm4(af[0], aoff+ks*32);
            ldsm4(af[1], aoff+16*ROWB+ks*32);
            ldsm4(af[2], aoff+TILEB+ks*32);
            ldsm4(af[3], aoff+TILEB+16*ROWB+ks*32);
#pragma unroll
            for(int np=0;np<4;++np) ldsm4(bb[np], boff+np*16*ROWB+ks*32);
#pragma unroll
            for(int mt=0;mt<2;++mt)
#pragma unroll
                for(int nt=0;nt<8;++nt){
                    int p=nt>>1,h=(nt&1)<<1;
                    mma16816(acc[mt][nt], af[mt],   bb[p][h], bb[p][h+1]);
                    mma16816(acc[mt][nt], af[2+mt], bb[p][h], bb[p][h+1]);
                }
#pragma unroll
            for(int np=0;np<4;++np) ldsm4(bb[np], boff+TILEB+np*16*ROWB+ks*32);
#pragma unroll
            for(int mt=0;mt<2;++mt)
#pragma unroll
                for(int nt=0;nt<8;++nt){
                    int p=nt>>1,h=(nt&1)<<1;
                    mma16816(acc[mt][nt], af[mt], bb[p][h], bb[p][h+1]);
                }
        }
        __syncthreads();
        if(it+2<nIt) load_stage(it+2);
    }

#pragma unroll
    for(int mt=0;mt<2;++mt){
        int rr=m0+m0w+mt*16+(lane>>2);
#pragma unroll
        for(int nt=0;nt<8;++nt){
            int c=n0+n0w+nt*8+((lane&3)<<1);
            float b0=bias?__ldg(bias+c):0.f, b1=bias?__ldg(bias+c+1):0.f;
#pragma unroll
            for(int hr=0;hr<2;++hr){
                int r=rr+hr*8;
                if(r>=M) continue;
                float v0=acc[mt][nt][hr*2]+b0, v1=acc[mt][nt][hr*2+1]+b1;
                if(mode==0){
                    *(float2*)(F0+(size_t)r*ldc+c)=make_float2(v0,v1);
                } else if(mode==1||mode==4){
                    if(mode==1){v0=fmaxf(v0,0.f);v1=fmaxf(v1,0.f);}
                    uint32_t hi,lo; split_pack(v0,v1,hi,lo);
                    *(uint32_t*)(H0+(size_t)r*ldc+c)=hi;
                    *(uint32_t*)(L0+(size_t)r*ldc+c)=lo;
                } else if(mode==2){
                    int rk=r+(r>=2304?16384:0);
                    uint32_t hi,lo; split_pack(v0,v1,hi,lo);
                    if(c<1024){
                        *(uint32_t*)(H0+(size_t)rk*1024+c)=hi;
                        *(uint32_t*)(L0+(size_t)rk*1024+c)=lo;
                        if(r>=2304) *(float2*)(F1+(size_t)(r-2304)*1024+c)=make_float2(v0,v1);
                    } else {
                        int cc=c-1024;
                        *(uint32_t*)(H1+(size_t)rk*1024+cc)=hi;
                        *(uint32_t*)(L1+(size_t)rk*1024+cc)=lo;
                        if(r>=2304) *(float2*)(F2+(size_t)(r-2304)*1024+cc)=make_float2(v0,v1);
                    }
                } else {
                    if(r<10240){
                        const float* resid=(r<2048)?F1+(size_t)r*1024+c:F2+(size_t)(r-2048)*1024+c;
                        float2 rv=*(const float2*)resid;
                        *(float2*)(F0+(size_t)r*1024+c)=make_float2(v0+rv.x,v1+rv.y);
                    } else {
                        v0=fminf(fmaxf(v0,-10.f),10.f); v1=fminf(fmaxf(v1,-10.f),10.f);
                        *(float2*)(F3+(size_t)(r-10240)*1024+c)=make_float2(v0,v1);
                    }
                }
            }
        }
    }
}

__global__ void __launch_bounds__(256,2) gemm_mma(
    const bf16* __restrict__ Ah_, const bf16* __restrict__ Al_, int lda,
    const bf16* __restrict__ Bh_, const bf16* __restrict__ Bl_, int ldb,
    const float* __restrict__ bias, int M, int K, int mode,
    float* __restrict__ F0, bf16* __restrict__ H0, bf16* __restrict__ L0, int ldc,
    bf16* __restrict__ H1, bf16* __restrict__ L1,
    float* __restrict__ F1, float* __restrict__ F2, float* __restrict__ F3)
{
    gemm_body(blockIdx.x, blockIdx.y, blockIdx.z, Ah_, Al_, lda, Bh_, Bl_, ldb,
              bias, M, K, mode, F0, H0, L0, ldc, H1, L1, F1, F2, F3);
}

#define QBLK 648
__global__ void __launch_bounds__(256,2) gemm_qkv(
    const bf16* __restrict__ cath, const bf16* __restrict__ catl,
    const bf16* __restrict__ wqh, const bf16* __restrict__ wql,
    const float* __restrict__ b_q, bf16* __restrict__ qh, bf16* __restrict__ ql,
    const bf16* __restrict__ wkvh, const bf16* __restrict__ wkvl,
    const float* __restrict__ b_kv, bf16* __restrict__ kh, bf16* __restrict__ kl,
    bf16* __restrict__ vh, bf16* __restrict__ vl,
    float* __restrict__ km, float* __restrict__ vm)
{
    int id=blockIdx.x;
    if(id<QBLK){
        gemm_body(id&7, id>>3, 0, cath+(size_t)4*BD, catl+(size_t)4*BD, Dm, wqh, wql, Dm,
                  b_q, QQm*BBm, Dm, 4, nullptr, qh, ql, Dm,
                  nullptr, nullptr, nullptr, nullptr, nullptr);
    } else {
        id-=QBLK;
        gemm_body(id&15, id>>4, 0, cath, catl, Dm, wkvh, wkvl, Dm,
                  b_kv, 164*BBm, Dm, 2, nullptr, kh, kl, 0,
                  vh, vl, km, vm, nullptr);
    }
}

// ---- attention kernels ----
#define FROWB 144
#define FTILE 9216

// QK^T: block=(qt,bh), Q staged once (fragments in regs), K staged per chunk (R13 best config).
__global__ void __launch_bounds__(128) k_qk(const int* __restrict__ past_len){
    __shared__ __align__(16) char sm[4*FTILE];
    const int tid=threadIdx.x, wid=tid>>5, lane=tid&31;
    const int qt=blockIdx.x, bh=blockIdx.y;
    const size_t headoff=(size_t)bh*64;
    const uint32_t sqb=smem_u32(sm), skb=sqb+2*FTILE;
    const int pl=past_len[0], m_kv=min(LLm,pl), m_m=min(MMm,pl/SEGm);
    const int lim1=MMm-m_m, lim2=36+(LLm-m_kv);
    const int r=tid>>1, hf=tid&1;
    {   // stage Q tile once
        int gq=min(qt*64+r,160);
        const bf16* sh_=g_qh+(size_t)gq*BD+headoff+hf*32;
        const bf16* sl_=g_ql+(size_t)gq*BD+headoff+hf*32;
        uint32_t d0=sqb+(uint32_t)r*FROWB+hf*64;
#pragma unroll
        for(int i=0;i<4;i++){ cp16(d0+i*16, sh_+i*8); cp16(d0+FTILE+i*16, sl_+i*8); }
        asm volatile("cp.async.commit_group;":::"memory");
        asm volatile("cp.async.wait_group 0;":::"memory");
        __syncthreads();
    }
    uint32_t qfh[4][4], qfl[4][4];
    {
        uint32_t qa=sqb+(uint32_t)(wid*16+(lane&15))*FROWB+((lane>>4)<<4);
#pragma unroll
        for(int s=0;s<4;s++){ ldsm4(qfh[s], qa+s*32); ldsm4(qfl[s], qa+FTILE+s*32); }
    }
    const int rlo=qt*64+wid*16+(lane>>2), rhi=rlo+8;
    const bool sumlo=(rlo==160), sumhi=(rhi==160);
    float* rowlo=g_scores+((size_t)bh*192+rlo)*448;
    float* rowhi=g_scores+((size_t)bh*192+rhi)*448;
#pragma unroll 1
    for(int kc=0;kc<7;kc++){
        __syncthreads();
        {
            int t=min(kc*64+r,KKm-1);
            const bf16 *kh_=g_kh+(size_t)t*BD+headoff+hf*32, *kl_=g_kl+(size_t)t*BD+headoff+hf*32;
            uint32_t dk=skb+(uint32_t)r*FROWB+hf*64;
#pragma unroll
            for(int i=0;i<4;i++){ cp16(dk+i*16, kh_+i*8); cp16(dk+FTILE+i*16, kl_+i*8); }
            asm volatile("cp.async.commit_group;":::"memory");
            asm volatile("cp.async.wait_group 0;":::"memory");
            __syncthreads();
        }
        float S[8][4];
#pragma unroll
        for(int i=0;i<8;i++){S[i][0]=0.f;S[i][1]=0.f;S[i][2]=0.f;S[i][3]=0.f;}
#pragma unroll
        for(int s=0;s<4;s++){
#pragma unroll
            for(int g=0;g<4;g++){
                uint32_t kaddr=skb+(uint32_t)(g*16+(lane&7)+((lane>>4)<<3))*FROWB+(((lane>>3)&1)<<4)+s*32;
                uint32_t kbh[4], kbl[4];
                ldsm4(kbh, kaddr);
                ldsm4(kbl, kaddr+FTILE);
                mma16816(S[2*g],   qfh[s], kbh[0], kbh[1]);
                mma16816(S[2*g+1], qfh[s], kbh[2], kbh[3]);
                mma16816(S[2*g],   qfl[s], kbh[0], kbh[1]);
                mma16816(S[2*g+1], qfl[s], kbh[2], kbh[3]);
                mma16816(S[2*g],   qfh[s], kbl[0], kbl[1]);
                mma16816(S[2*g+1], qfh[s], kbl[2], kbl[3]);
            }
        }
#pragma unroll
        for(int nt=0;nt<8;nt++){
            int c0=kc*64+nt*8+((lane&3)<<1), c1=c0+1;
            bool b0=(c0<lim1)||(c0>=36&&c0<lim2)||(c0>=KKm);
            bool b1=(c1<lim1)||(c1>=36&&c1<lim2)||(c1>=KKm);
            float s0=(b0||(sumlo&&c0<MMm))?NEG_INF_F:S[nt][0]*0.125f;
            float s1=(b1||(sumlo&&c1<MMm))?NEG_INF_F:S[nt][1]*0.125f;
            float s2=(b0||(sumhi&&c0<MMm))?NEG_INF_F:S[nt][2]*0.125f;
            float s3=(b1||(sumhi&&c1<MMm))?NEG_INF_F:S[nt][3]*0.125f;
            *(float2*)(rowlo+c0)=make_float2(s0,s1);
            *(float2*)(rowhi+c0)=make_float2(s2,s3);
        }
    }
}

// softmax: reads fp32 scores, writes pre-split bf16 probabilities (hi/lo) for k_pv.
__global__ void __launch_bounds__(128) k_softmax2(){
    __shared__ float sred[4];
    size_t rowoff=(size_t)blockIdx.x*448;
    const float2* row=(const float2*)(g_scores+rowoff);
    int tid=threadIdx.x, lane=tid&31, w=tid>>5;
    float2 v2[2];
    float mx=-3.4e38f;
    v2[0]=row[tid];                              // c = 2t, 2t+1 (covers 0..255)
    mx=fmaxf(mx,fmaxf(v2[0].x,v2[0].y));
    if(tid<96){ v2[1]=row[tid+128]; mx=fmaxf(mx,fmaxf(v2[1].x,v2[1].y)); }
    else { v2[1]=make_float2(-3.4e38f,-3.4e38f); }
#pragma unroll
    for(int o=16;o;o>>=1) mx=fmaxf(mx,__shfl_xor_sync(0xffffffffu,mx,o));
    if(lane==0) sred[w]=mx;
    __syncthreads();
    mx=fmaxf(fmaxf(sred[0],sred[1]),fmaxf(sred[2],sred[3]));
    __syncthreads();
    float s=0.f;
    v2[0].x=__expf(v2[0].x-mx); v2[0].y=__expf(v2[0].y-mx); s+=v2[0].x+v2[0].y;
    if(tid<96){ v2[1].x=__expf(v2[1].x-mx); v2[1].y=__expf(v2[1].y-mx); s+=v2[1].x+v2[1].y; }
#pragma unroll
    for(int o=16;o;o>>=1) s+=__shfl_xor_sync(0xffffffffu,s,o);
    if(lane==0) sred[w]=s;
    __syncthreads();
    s=sred[0]+sred[1]+sred[2]+sred[3];
    float rinv=1.f/s;
    uint32_t* ph=(uint32_t*)(g_ph+rowoff);
    uint32_t* pl=(uint32_t*)(g_pl+rowoff);
    uint32_t hi,lo;
    split_pack(v2[0].x*rinv, v2[0].y*rinv, hi, lo);
    ph[tid]=hi; pl[tid]=lo;
    if(tid<96){
        split_pack(v2[1].x*rinv, v2[1].y*rinv, hi, lo);
        ph[tid+128]=hi; pl[tid+128]=lo;
    }
}

// P @ V: P staged via plain cp.async from pre-split buffers (no convert in critical path).
__global__ void __launch_bounds__(128) k_pv(){
    __shared__ __align__(16) char sm[4*FTILE];
    const int tid=threadIdx.x, wid=tid>>5, lane=tid&31;
    const int qt=blockIdx.x, bh=blockIdx.y;
    const size_t headoff=(size_t)bh*64;
    const uint32_t spb=smem_u32(sm), svb=spb+2*FTILE;
    const int r=tid>>1, hf=tid&1;
    float out[8][4];
#pragma unroll
    for(int i=0;i<8;i++){out[i][0]=0.f;out[i][1]=0.f;out[i][2]=0.f;out[i][3]=0.f;}
#pragma unroll 1
    for(int kc=0;kc<7;kc++){
        __syncthreads();
        {
            int t=min(kc*64+r,KKm-1);
            const bf16 *vh_=g_vh+(size_t)t*BD+headoff+hf*32, *vl_=g_vl+(size_t)t*BD+headoff+hf*32;
            const bf16 *ph_=g_ph+((size_t)bh*192+qt*64+r)*448+kc*64+hf*32;
            const bf16 *pl2_=g_pl+((size_t)bh*192+qt*64+r)*448+kc*64+hf*32;
            uint32_t dv=svb+(uint32_t)r*FROWB+hf*64;
            uint32_t dp=spb+(uint32_t)r*FROWB+hf*64;
#pragma unroll
            for(int i=0;i<4;i++){
                cp16(dv+i*16, vh_+i*8); cp16(dv+FTILE+i*16, vl_+i*8);
                cp16(dp+i*16, ph_+i*8); cp16(dp+FTILE+i*16, pl2_+i*8);
            }
            asm volatile("cp.async.commit_group;":::"memory");
            asm volatile("cp.async.wait_group 0;":::"memory");
            __syncthreads();
        }
        uint32_t pa=spb+(uint32_t)(wid*16+(lane&15))*FROWB+((lane>>4)<<4);
#pragma unroll
        for(int s=0;s<4;s++){
            uint32_t ph[4], pl_[4];
            ldsm4(ph, pa+s*32);
            ldsm4(pl_, pa+FTILE+s*32);
#pragma unroll
            for(int j=0;j<4;j++){
                uint32_t va=svb+(uint32_t)(s*16+(lane&15))*FROWB+(uint32_t)(j*32+((lane>>4)<<4));
                uint32_t vh4[4], vl4[4];
                ldsm4t(vh4, va);
                ldsm4t(vl4, va+FTILE);
                mma16816(out[2*j],   ph,  vh4[0], vh4[1]);
                mma16816(out[2*j+1], ph,  vh4[2], vh4[3]);
                mma16816(out[2*j],   pl_, vh4[0], vh4[1]);
                mma16816(out[2*j+1], pl_, vh4[2], vh4[3]);
                mma16816(out[2*j],   ph,  vl4[0], vl4[1]);
                mma16816(out[2*j+1], ph,  vl4[2], vl4[3]);
            }
        }
    }
    int glo=qt*64+wid*16+(lane>>2), ghi=glo+8;
#pragma unroll
    for(int nt=0;nt<8;nt++){
        int d=nt*8+((lane&3)<<1);
        if(glo<QQm){
            uint32_t hi,lo;
            split_pack(out[nt][0], out[nt][1], hi, lo);
            *(uint32_t*)(g_ah+(size_t)glo*BD+headoff+d)=hi;
            *(uint32_t*)(g_al+(size_t)glo*BD+headoff+d)=lo;
        }
        if(ghi<QQm){
            uint32_t hi,lo;
            split_pack(out[nt][2], out[nt][3], hi, lo);
            *(uint32_t*)(g_ah+(size_t)ghi*BD+headoff+d)=hi;
            *(uint32_t*)(g_al+(size_t)ghi*BD+headoff+d)=lo;
        }
    }
}

// ---- fp32 -> (hi,lo) bf16 split ----
__device__ __forceinline__ void split4(float4 v, bf162* hp, bf162* lp, size_t i2){
    bf16 h0=__float2bfloat16(v.x), h1=__float2bfloat16(v.y);
    bf16 h2=__float2bfloat16(v.z), h3=__float2bfloat16(v.w);
    hp[i2]=__halves2bfloat162(h0,h1); hp[i2+1]=__halves2bfloat162(h2,h3);
    lp[i2]=__halves2bfloat162(__float2bfloat16(v.x-__bfloat162float(h0)),__float2bfloat16(v.y-__bfloat162float(h1)));
    lp[i2+1]=__halves2bfloat162(__float2bfloat16(v.z-__bfloat162float(h2)),__float2bfloat16(v.w-__bfloat162float(h3)));
}
__global__ void k_split(const float* __restrict__ s, bf16* __restrict__ h, bf16* __restrict__ l){
    size_t i=(size_t)blockIdx.x*blockDim.x+threadIdx.x;
    split4(((const float4*)s)[i], (bf162*)h, (bf162*)l, 2*i);
}
__global__ void k_split_mir(const float* __restrict__ s, bf16* __restrict__ h, bf16* __restrict__ l,
                            float* __restrict__ mir){
    size_t i=(size_t)blockIdx.x*blockDim.x+threadIdx.x;
    float4 v=((const float4*)s)[i];
    split4(v, (bf162*)h, (bf162*)l, 2*i);
    size_t half=(size_t)128*BD/4;
    if(i>=half) ((float4*)mir)[i-half]=v;
}

__device__ __forceinline__ float bsum(float v, float* sh){
    int lane=threadIdx.x&31, w=threadIdx.x>>5;
#pragma unroll
    for(int o=16;o;o>>=1) v+=__shfl_xor_sync(0xffffffffu,v,o);
    if(lane==0) sh[w]=v;
    __syncthreads();
    if(w==0){ float r=(lane<8)?sh[lane]:0.f;
#pragma unroll
        for(int o=4;o;o>>=1) r+=__shfl_xor_sync(0xffffffffu,r,o);
        if(lane==0) sh[0]=r; }
    __syncthreads(); float o=sh[0]; __syncthreads(); return o;
}
__device__ __forceinline__ float4 ln_core(float4 x, const float* gw, const float* bw, int tid, float* sh){
    float mu=bsum(x.x+x.y+x.z+x.w,sh)*(1.f/Dm);
    float d0=x.x-mu,d1=x.y-mu,d2=x.z-mu,d3=x.w-mu;
    float var=bsum(d0*d0+d1*d1+d2*d2+d3*d3,sh)*(1.f/Dm);
    float inv=rsqrtf(var+EPS_LN);
    float4 g4=((const float4*)gw)[tid], b4=((const float4*)bw)[tid];
    return make_float4(d0*inv*g4.x+b4.x, d1*inv*g4.y+b4.y, d2*inv*g4.z+b4.z, d3*inv*g4.w+b4.w);
}
__global__ void __launch_bounds__(256) k_ln_in(const float* __restrict__ rc, const float* __restrict__ utt,
                                               const float* __restrict__ gw, const float* __restrict__ bw){
    __shared__ float sh[8];
    int row=blockIdx.x, tid=threadIdx.x;
    const float* src=(row<RRm*BBm)?rc+(size_t)row*Dm:utt+(size_t)(row-RRm*BBm)*Dm;
    float4 o=ln_core(((const float4*)src)[tid],gw,bw,tid,sh);
    size_t base=(size_t)(4*BBm+row)*Dm;
    ((float4*)(g_cat+base))[tid]=o;
    split4(o,(bf162*)(g_cat_h+base),(bf162*)(g_cat_l+base),2*(size_t)tid);
}
__global__ void __launch_bounds__(256) k_ln_ff(const float* __restrict__ gw, const float* __restrict__ bw){
    __shared__ float sh[8];
    int row=blockIdx.x, tid=threadIdx.x;
    size_t base=(size_t)row*Dm;
    float4 o=ln_core(((const float4*)(g_res+base))[tid],gw,bw,tid,sh);
    split4(o,(bf162*)(g_ffin_h+base),(bf162*)(g_ffin_l+base),2*(size_t)tid);
}
__global__ void __launch_bounds__(256) k_ln_final(const float* __restrict__ gw, const float* __restrict__ bw,
                                                  float* __restrict__ dout){
    __shared__ float sh[8];
    int row=blockIdx.x, tid=threadIdx.x;
    float4 a=((const float4*)(g_res+(size_t)row*Dm))[tid];
    float4 f=((const float4*)(g_ff2+(size_t)row*Dm))[tid];
    float4 g=((const float4*)(g_ff2b+(size_t)row*Dm))[tid];
    float4 o=ln_core(make_float4(a.x+f.x+g.x,a.y+f.y+g.y,a.z+f.z+g.z,a.w+f.w+g.w),gw,bw,tid,sh);
    float* dst=(row<RRm*BBm)?dout+S1_OFF+(size_t)row*Dm:dout+S0_OFF+(size_t)(row-RRm*BBm)*Dm;
    ((float4*)dst)[tid]=o;
}
__global__ void k_summary(){
    int e=blockIdx.x*blockDim.x+threadIdx.x;
    float s=0.f;
#pragma unroll 8
    for(int t=0;t<UUm;t++) s+=g_cat[(size_t)(36+t)*BD+e];
    float v=s*(1.f/SEGm);
    size_t o=(size_t)164*BD+e;
    bf16 h=__float2bfloat16(v);
    g_cat_h[o]=h; g_cat_l[o]=__float2bfloat16(v-__bfloat162float(h));
}

extern "C" void kernel_launch(void* const* d_in, const int* in_sizes, int n_in,
                              void* d_out_v, int out_size) {
    const float* utterance=(const float*)d_in[0];
    const float* right_ctx=(const float*)d_in[1];
    const float* mems_in=(const float*)d_in[2];
    const float* state_mems=(const float*)d_in[3];
    const float* lc_key=(const float*)d_in[4];
    const float* lc_val=(const float*)d_in[5];
    const float* W_kv=(const float*)d_in[6];
    const float* b_kv=(const float*)d_in[7];
    const float* W_q=(const float*)d_in[8];
    const float* b_q=(const float*)d_in[9];
    const float* W_out=(const float*)d_in[10];
    const float* b_out=(const float*)d_in[11];
    const float* ln_in_g=(const float*)d_in[12];
    const float* ln_in_b=(const float*)d_in[13];
    const float* ln_ff_g=(const float*)d_in[14];
    const float* ln_ff_b=(const float*)d_in[15];
    const float* W_ff1=(const float*)d_in[16];
    const float* b_ff1=(const float*)d_in[17];
    const float* W_ff2=(const float*)d_in[18];
    const float* b_ff2=(const float*)d_in[19];
    const float* ln_out_g=(const float*)d_in[20];
    const float* ln_out_b=(const float*)d_in[21];
    const int* past_len=(const int*)d_in[22];
    float* dout=(float*)d_out_v;

    float *res,*ff2b_,*ff2c;
    bf16 *cath,*catl,*qh,*ql,*kh,*kl,*vh,*vl,*ah,*al;
    bf16 *ffinh,*ffinl,*ffhh,*ffhl;
    bf16 *wqh,*wql,*wkvh,*wkvl,*woh,*wol,*w1h,*w1l,*w2h,*w2l;
    cudaGetSymbolAddress((void**)&res,g_res);
    cudaGetSymbolAddress((void**)&ff2b_,g_ff2);
    cudaGetSymbolAddress((void**)&ff2c,g_ff2b);
    cudaGetSymbolAddress((void**)&cath,g_cat_h); cudaGetSymbolAddress((void**)&catl,g_cat_l);
    cudaGetSymbolAddress((void**)&qh,g_qh); cudaGetSymbolAddress((void**)&ql,g_ql);
    cudaGetSymbolAddress((void**)&kh,g_kh); cudaGetSymbolAddress((void**)&kl,g_kl);
    cudaGetSymbolAddress((void**)&vh,g_vh); cudaGetSymbolAddress((void**)&vl,g_vl);
    cudaGetSymbolAddress((void**)&ah,g_ah); cudaGetSymbolAddress((void**)&al,g_al);
    cudaGetSymbolAddress((void**)&ffinh,g_ffin_h); cudaGetSymbolAddress((void**)&ffinl,g_ffin_l);
    cudaGetSymbolAddress((void**)&ffhh,g_ffh_h); cudaGetSymbolAddress((void**)&ffhl,g_ffh_l);
    cudaGetSymbolAddress((void**)&wqh,g_wq_h); cudaGetSymbolAddress((void**)&wql,g_wq_l);
    cudaGetSymbolAddress((void**)&wkvh,g_wkv_h); cudaGetSymbolAddress((void**)&wkvl,g_wkv_l);
    cudaGetSymbolAddress((void**)&woh,g_wo_h); cudaGetSymbolAddress((void**)&wol,g_wo_l);
    cudaGetSymbolAddress((void**)&w1h,g_w1_h); cudaGetSymbolAddress((void**)&w1l,g_w1_l);
    cudaGetSymbolAddress((void**)&w2h,g_w2_h); cudaGetSymbolAddress((void**)&w2l,g_w2_l);

    cudaFuncSetAttribute(gemm_mma, cudaFuncAttributeMaxDynamicSharedMemorySize, GEMM_SMEM);
    cudaFuncSetAttribute(gemm_qkv, cudaFuncAttributeMaxDynamicSharedMemorySize, GEMM_SMEM);

    k_split<<<(4*BD/4)/256,256>>>(state_mems, cath, catl);
    k_split<<<(Dm*Dm/4)/256,256>>>(W_q, wqh, wql);
    k_ln_in<<<TTm*BBm,256>>>(right_ctx, utterance, ln_in_g, ln_in_b);
    k_summary<<<BD/256,256>>>();
    k_split<<<(2*Dm*Dm/4)/256,256>>>(W_kv, wkvh, wkvl);
    // merged Q + KV projection
    gemm_qkv<<<QBLK+16*82,256,GEMM_SMEM>>>(cath, catl,
        wqh, wql, b_q, qh, ql,
        wkvh, wkvl, b_kv, kh, kl, vh, vl,
        dout+S4_OFF+(size_t)128*BD, dout+S5_OFF+(size_t)128*BD);
    // cached local-context K/V -> split middles + fp32 mirror to dout
    k_split_mir<<<((size_t)LLm*BD/4)/256,256>>>(lc_key, kh+(size_t)36*BD, kl+(size_t)36*BD, dout+S4_OFF);
    k_split_mir<<<((size_t)LLm*BD/4)/256,256>>>(lc_val, vh+(size_t)36*BD, vl+(size_t)36*BD, dout+S5_OFF);
    // attention: qt-blocked QK^T (R13), softmax with pre-split output, cp.async-only PV staging
    k_qk<<<dim3(3,1024),128>>>(past_len);
    k_softmax2<<<1024*192,128>>>();
    k_pv<<<dim3(3,1024),128>>>();
    k_split<<<(Dm*Dm/4)/256,256>>>(W_out, woh, wol);
    // W_out projection with fused residual + clip (mode 3)
    gemm_mma<<<dim3(8,81),256,GEMM_SMEM>>>(ah, al, Dm, woh, wol, Dm,
        b_out, QQm*BBm, Dm, 3, res, nullptr, nullptr, Dm, nullptr, nullptr,
        (float*)right_ctx, (float*)utterance, dout+S2_OFF);
    // FFN
    k_ln_ff<<<TTm*BBm,256>>>(ln_ff_g, ln_ff_b);
    k_split<<<((size_t)FFNm*Dm/4)/256,256>>>(W_ff1, w1h, w1l);
    gemm_mma<<<dim3(32,80),256,GEMM_SMEM>>>(ffinh, ffinl, Dm, w1h, w1l, Dm,
        b_ff1, TTm*BBm, Dm, 1, nullptr, ffhh, ffhl, FFNm, nullptr, nullptr, nullptr, nullptr, nullptr);
    k_split<<<((size_t)FFNm*Dm/4)/256,256>>>(W_ff2, w2h, w2l);
    // FF2 split-K x2
    gemm_mma<<<dim3(8,80,2),256,GEMM_SMEM>>>(ffhh, ffhl, FFNm, w2h, w2l, FFNm,
        b_ff2, TTm*BBm, 2048, 0, ff2b_, nullptr, nullptr, Dm, nullptr, nullptr,
        nullptr, nullptr, ff2c);
    k_ln_final<<<TTm*BBm,256>>>(ln_out_g, ln_out_b, dout);
    // state-carry
    cudaMemcpyAsync(dout+S3_OFF, state_mems+BD, (size_t)3*BD*sizeof(float), cudaMemcpyDeviceToDevice, 0);
    cudaMemcpyAsync(dout+S3_OFF+(size_t)3*BD, mems_in, (size_t)BD*sizeof(float), cudaMemcpyDeviceToDevice, 0);
}

// round 16
// speedup vs baseline: 1.0440x; 1.0440x over previous
#include <cuda_runtime.h>
#include <cuda_bf16.h>
#include <cstdint>
#include <cstddef>

#define Dm 1024
#define FFNm 4096
#define SEGm 128
#define LLm 256
#define MMm 4
#define BBm 64
#define UUm 128
#define RRm 32
#define TTm 160
#define QQm 161
#define KKm 420
#define BD (BBm*Dm)
#define NEG_INF_F (-1e8f)
#define EPS_LN 1e-5f
#define S0_OFF 0u
#define S1_OFF 8388608u
#define S2_OFF 10485760u
#define S3_OFF 10551296u
#define S4_OFF 10813440u
#define S5_OFF 27590656u

typedef __nv_bfloat16 bf16;
typedef __nv_bfloat162 bf162;

__device__ float g_cat[165*BD];
__device__ float g_res[TTm*BD];
__device__ float g_ff2[TTm*BD];
__device__ float g_ff2b[TTm*BD];
__device__ float g_scores[(size_t)1024*192*448];
__device__ bf16 g_ph[(size_t)1024*192*448], g_pl[(size_t)1024*192*448];
__device__ bf16 g_cat_h[165*BD], g_cat_l[165*BD];
__device__ bf16 g_qh[QQm*BD], g_ql[QQm*BD];
__device__ bf16 g_kh[448*BD], g_kl[448*BD];
__device__ bf16 g_vh[448*BD], g_vl[448*BD];
__device__ bf16 g_ah[QQm*BD], g_al[QQm*BD];
__device__ bf16 g_ffin_h[TTm*BD], g_ffin_l[TTm*BD];
__device__ bf16 g_ffh_h[(size_t)TTm*BBm*FFNm], g_ffh_l[(size_t)TTm*BBm*FFNm];
__device__ bf16 g_wq_h[Dm*Dm], g_wq_l[Dm*Dm];
__device__ bf16 g_wkv_h[2*Dm*Dm], g_wkv_l[2*Dm*Dm];
__device__ bf16 g_wo_h[Dm*Dm], g_wo_l[Dm*Dm];
__device__ bf16 g_w1_h[FFNm*Dm], g_w1_l[FFNm*Dm];
__device__ bf16 g_w2_h[Dm*FFNm], g_w2_l[Dm*FFNm];

__device__ __forceinline__ uint32_t smem_u32(const void* p){
    uint32_t a; asm("{ .reg .u64 t; cvta.to.shared.u64 t, %1; cvt.u32.u64 %0, t; }":"=r"(a):"l"(p)); return a;
}
__device__ __forceinline__ void cp16(uint32_t dst, const void* src){
    asm volatile("cp.async.cg.shared.global [%0], [%1], 16;"::"r"(dst),"l"(src));
}
__device__ __forceinline__ void ldsm4(uint32_t* r, uint32_t addr){
    asm volatile("ldmatrix.sync.aligned.m8n8.x4.shared.b16 {%0,%1,%2,%3}, [%4];"
        :"=r"(r[0]),"=r"(r[1]),"=r"(r[2]),"=r"(r[3]):"r"(addr));
}
__device__ __forceinline__ void ldsm4t(uint32_t* r, uint32_t addr){
    asm volatile("ldmatrix.sync.aligned.m8n8.x4.trans.shared.b16 {%0,%1,%2,%3}, [%4];"
        :"=r"(r[0]),"=r"(r[1]),"=r"(r[2]),"=r"(r[3]):"r"(addr));
}
__device__ __forceinline__ void mma16816(float* c, const uint32_t* a, uint32_t b0, uint32_t b1){
    asm volatile("mma.sync.aligned.m16n8k16.row.col.f32.bf16.bf16.f32 "
        "{%0,%1,%2,%3}, {%4,%5,%6,%7}, {%8,%9}, {%0,%1,%2,%3};"
        :"+f"(c[0]),"+f"(c[1]),"+f"(c[2]),"+f"(c[3])
        :"r"(a[0]),"r"(a[1]),"r"(a[2]),"r"(a[3]),"r"(b0),"r"(b1));
}
__device__ __forceinline__ void split_pack(float a, float b, uint32_t& hi, uint32_t& lo){
    bf16 ha=__float2bfloat16(a), hb=__float2bfloat16(b);
    hi=(uint32_t)__bfloat16_as_ushort(ha)|((uint32_t)__bfloat16_as_ushort(hb)<<16);
    bf16 la=__float2bfloat16(a-__bfloat162float(ha)), lb=__float2bfloat16(b-__bfloat162float(hb));
    lo=(uint32_t)__bfloat16_as_ushort(la)|((uint32_t)__bfloat16_as_ushort(lb)<<16);
}

// ---- HMMA split-bf16 GEMM body (tile 128x128, BK=32, fused 3-pass, 2-stage) ----
#define ROWB 80
#define TILEB 10240
#define STAGEB 40960
#define GEMM_SMEM (2*STAGEB)
__device__ __noinline__ void gemm_body(
    int bx, int by, int bz,
    const bf16* Ah_, const bf16* Al_, int lda,
    const bf16* Bh_, const bf16* Bl_, int ldb,
    const float* bias, int M, int K, int mode,
    float* F0, bf16* H0, bf16* L0, int ldc,
    bf16* H1, bf16* L1,
    float* F1, float* F2, float* F3)
{
    extern __shared__ __align__(16) char smem[];
    const int tid=threadIdx.x, wid=tid>>5, lane=tid&31;
    const int m0=by*128, n0=bx*128;
    const int m0w=(wid>>1)*32, n0w=(wid&1)*64;
    const uint32_t sb=smem_u32(smem);
    const int nIt=K>>5;
    const int kbase=bz*K;
    Ah_+=kbase; Al_+=kbase; Bh_+=kbase; Bl_+=kbase;
    if(bz==1){ F0=F3; bias=nullptr; }

    float acc[2][8][4];
#pragma unroll
    for(int i=0;i<2;i++)
#pragma unroll
        for(int j=0;j<8;j++)
#pragma unroll
            for(int l=0;l<4;l++) acc[i][j][l]=0.f;

    const int lrow=tid>>1, le0=(tid&1)*16;
    int gra=m0+lrow; if(gra>=M) gra=M-1;
    const int grb=n0+lrow;

    auto load_stage=[&](int it){
        int kk=it<<5;
        uint32_t st=sb+(it&1)*STAGEB;
        uint32_t rb=st+(uint32_t)lrow*ROWB+le0*2;
        cp16(rb,          Ah_+(size_t)gra*lda+kk+le0);
        cp16(rb+16,       Ah_+(size_t)gra*lda+kk+le0+8);
        cp16(rb+TILEB,    Al_+(size_t)gra*lda+kk+le0);
        cp16(rb+TILEB+16, Al_+(size_t)gra*lda+kk+le0+8);
        cp16(rb+2*TILEB,    Bh_+(size_t)grb*ldb+kk+le0);
        cp16(rb+2*TILEB+16, Bh_+(size_t)grb*ldb+kk+le0+8);
        cp16(rb+3*TILEB,    Bl_+(size_t)grb*ldb+kk+le0);
        cp16(rb+3*TILEB+16, Bl_+(size_t)grb*ldb+kk+le0+8);
        asm volatile("cp.async.commit_group;":::"memory");
    };

    load_stage(0); load_stage(1);
    for(int it=0; it<nIt; ++it){
        asm volatile("cp.async.wait_group 1;":::"memory");
        __syncthreads();
        uint32_t st=sb+(it&1)*STAGEB;
        uint32_t aoff=st+(uint32_t)(m0w+(lane&15))*ROWB+((lane>>4)<<4);
        uint32_t boff=st+2*TILEB+(uint32_t)(n0w+(lane&7)+((lane>>4)<<3))*ROWB+(((lane>>3)&1)<<4);
#pragma unroll
        for(int ks=0;ks<2;++ks){
            uint32_t af[4][4], bb[4][4];
            ldsm4(af[0], aoff+ks*32);
            ldsm4(af[1], aoff+16*ROWB+ks*32);
            ldsm4(af[2], aoff+TILEB+ks*32);
            ldsm4(af[3], aoff+TILEB+16*ROWB+ks*32);
#pragma unroll
            for(int np=0;np<4;++np) ldsm4(bb[np], boff+np*16*ROWB+ks*32);
#pragma unroll
            for(int mt=0;mt<2;++mt)
#pragma unroll
                for(int nt=0;nt<8;++nt){
                    int p=nt>>1,h=(nt&1)<<1;
                    mma16816(acc[mt][nt], af[mt],   bb[p][h], bb[p][h+1]);
                    mma16816(acc[mt][nt], af[2+mt], bb[p][h], bb[p][h+1]);
                }
#pragma unroll
            for(int np=0;np<4;++np) ldsm4(bb[np], boff+TILEB+np*16*ROWB+ks*32);
#pragma unroll
            for(int mt=0;mt<2;++mt)
#pragma unroll
                for(int nt=0;nt<8;++nt){
                    int p=nt>>1,h=(nt&1)<<1;
                    mma16816(acc[mt][nt], af[mt], bb[p][h], bb[p][h+1]);
                }
        }
        __syncthreads();
        if(it+2<nIt) load_stage(it+2);
    }

#pragma unroll
    for(int mt=0;mt<2;++mt){
        int rr=m0+m0w+mt*16+(lane>>2);
#pragma unroll
        for(int nt=0;nt<8;++nt){
            int c=n0+n0w+nt*8+((lane&3)<<1);
            float b0=bias?__ldg(bias+c):0.f, b1=bias?__ldg(bias+c+1):0.f;
#pragma unroll
            for(int hr=0;hr<2;++hr){
                int r=rr+hr*8;
                if(r>=M) continue;
                float v0=acc[mt][nt][hr*2]+b0, v1=acc[mt][nt][hr*2+1]+b1;
                if(mode==0){
                    *(float2*)(F0+(size_t)r*ldc+c)=make_float2(v0,v1);
                } else if(mode==1||mode==4){
                    if(mode==1){v0=fmaxf(v0,0.f);v1=fmaxf(v1,0.f);}
                    uint32_t hi,lo; split_pack(v0,v1,hi,lo);
                    *(uint32_t*)(H0+(size_t)r*ldc+c)=hi;
                    *(uint32_t*)(L0+(size_t)r*ldc+c)=lo;
                } else if(mode==2){
                    int rk=r+(r>=2304?16384:0);
                    uint32_t hi,lo; split_pack(v0,v1,hi,lo);
                    if(c<1024){
                        *(uint32_t*)(H0+(size_t)rk*1024+c)=hi;
                        *(uint32_t*)(L0+(size_t)rk*1024+c)=lo;
                        if(r>=2304) *(float2*)(F1+(size_t)(r-2304)*1024+c)=make_float2(v0,v1);
                    } else {
                        int cc=c-1024;
                        *(uint32_t*)(H1+(size_t)rk*1024+cc)=hi;
                        *(uint32_t*)(L1+(size_t)rk*1024+cc)=lo;
                        if(r>=2304) *(float2*)(F2+(size_t)(r-2304)*1024+cc)=make_float2(v0,v1);
                    }
                } else {
                    if(r<10240){
                        const float* resid=(r<2048)?F1+(size_t)r*1024+c:F2+(size_t)(r-2048)*1024+c;
                        float2 rv=*(const float2*)resid;
                        *(float2*)(F0+(size_t)r*1024+c)=make_float2(v0+rv.x,v1+rv.y);
                    } else {
                        v0=fminf(fmaxf(v0,-10.f),10.f); v1=fminf(fmaxf(v1,-10.f),10.f);
                        *(float2*)(F3+(size_t)(r-10240)*1024+c)=make_float2(v0,v1);
                    }
                }
            }
        }
    }
}

__global__ void __launch_bounds__(256,2) gemm_mma(
    const bf16* __restrict__ Ah_, const bf16* __restrict__ Al_, int lda,
    const bf16* __restrict__ Bh_, const bf16* __restrict__ Bl_, int ldb,
    const float* __restrict__ bias, int M, int K, int mode,
    float* __restrict__ F0, bf16* __restrict__ H0, bf16* __restrict__ L0, int ldc,
    bf16* __restrict__ H1, bf16* __restrict__ L1,
    float* __restrict__ F1, float* __restrict__ F2, float* __restrict__ F3)
{
    gemm_body(blockIdx.x, blockIdx.y, blockIdx.z, Ah_, Al_, lda, Bh_, Bl_, ldb,
              bias, M, K, mode, F0, H0, L0, ldc, H1, L1, F1, F2, F3);
}

#define QBLK 648
__global__ void __launch_bounds__(256,2) gemm_qkv(
    const bf16* __restrict__ cath, const bf16* __restrict__ catl,
    const bf16* __restrict__ wqh, const bf16* __restrict__ wql,
    const float* __restrict__ b_q, bf16* __restrict__ qh, bf16* __restrict__ ql,
    const bf16* __restrict__ wkvh, const bf16* __restrict__ wkvl,
    const float* __restrict__ b_kv, bf16* __restrict__ kh, bf16* __restrict__ kl,
    bf16* __restrict__ vh, bf16* __restrict__ vl,
    float* __restrict__ km, float* __restrict__ vm)
{
    int id=blockIdx.x;
    if(id<QBLK){
        gemm_body(id&7, id>>3, 0, cath+(size_t)4*BD, catl+(size_t)4*BD, Dm, wqh, wql, Dm,
                  b_q, QQm*BBm, Dm, 4, nullptr, qh, ql, Dm,
                  nullptr, nullptr, nullptr, nullptr, nullptr);
    } else {
        id-=QBLK;
        gemm_body(id&15, id>>4, 0, cath, catl, Dm, wkvh, wkvl, Dm,
                  b_kv, 164*BBm, Dm, 2, nullptr, kh, kl, 0,
                  vh, vl, km, vm, nullptr);
    }
}

// ---- attention kernels ----
#define FROWB 144
#define FTILE 9216

// QK^T (R13 structure) + online softmax stats + fused pass-2 writing pre-split P.
__global__ void __launch_bounds__(128) k_qk(const int* __restrict__ past_len){
    __shared__ __align__(16) char sm[4*FTILE];
    const int tid=threadIdx.x, wid=tid>>5, lane=tid&31;
    const int qt=blockIdx.x, bh=blockIdx.y;
    const size_t headoff=(size_t)bh*64;
    const uint32_t sqb=smem_u32(sm), skb=sqb+2*FTILE;
    const int pl=past_len[0], m_kv=min(LLm,pl), m_m=min(MMm,pl/SEGm);
    const int lim1=MMm-m_m, lim2=36+(LLm-m_kv);
    const int r=tid>>1, hf=tid&1;
    {   // stage Q tile once
        int gq=min(qt*64+r,160);
        const bf16* sh_=g_qh+(size_t)gq*BD+headoff+hf*32;
        const bf16* sl_=g_ql+(size_t)gq*BD+headoff+hf*32;
        uint32_t d0=sqb+(uint32_t)r*FROWB+hf*64;
#pragma unroll
        for(int i=0;i<4;i++){ cp16(d0+i*16, sh_+i*8); cp16(d0+FTILE+i*16, sl_+i*8); }
        asm volatile("cp.async.commit_group;":::"memory");
        asm volatile("cp.async.wait_group 0;":::"memory");
        __syncthreads();
    }
    uint32_t qfh[4][4], qfl[4][4];
    {
        uint32_t qa=sqb+(uint32_t)(wid*16+(lane&15))*FROWB+((lane>>4)<<4);
#pragma unroll
        for(int s=0;s<4;s++){ ldsm4(qfh[s], qa+s*32); ldsm4(qfl[s], qa+FTILE+s*32); }
    }
    const int rlo=qt*64+wid*16+(lane>>2), rhi=rlo+8;
    const bool sumlo=(rlo==160), sumhi=(rhi==160);
    float* rowlo=g_scores+((size_t)bh*192+rlo)*448;
    float* rowhi=g_scores+((size_t)bh*192+rhi)*448;
    float mlo=-3e38f, mhi=-3e38f, llo=0.f, lhi=0.f;
#pragma unroll 1
    for(int kc=0;kc<7;kc++){
        __syncthreads();
        {
            int t=min(kc*64+r,KKm-1);
            const bf16 *kh_=g_kh+(size_t)t*BD+headoff+hf*32, *kl_=g_kl+(size_t)t*BD+headoff+hf*32;
            uint32_t dk=skb+(uint32_t)r*FROWB+hf*64;
#pragma unroll
            for(int i=0;i<4;i++){ cp16(dk+i*16, kh_+i*8); cp16(dk+FTILE+i*16, kl_+i*8); }
            asm volatile("cp.async.commit_group;":::"memory");
            asm volatile("cp.async.wait_group 0;":::"memory");
            __syncthreads();
        }
        float S[8][4];
#pragma unroll
        for(int i=0;i<8;i++){S[i][0]=0.f;S[i][1]=0.f;S[i][2]=0.f;S[i][3]=0.f;}
#pragma unroll
        for(int s=0;s<4;s++){
#pragma unroll
            for(int g=0;g<4;g++){
                uint32_t kaddr=skb+(uint32_t)(g*16+(lane&7)+((lane>>4)<<3))*FROWB+(((lane>>3)&1)<<4)+s*32;
                uint32_t kbh[4], kbl[4];
                ldsm4(kbh, kaddr);
                ldsm4(kbl, kaddr+FTILE);
                mma16816(S[2*g],   qfh[s], kbh[0], kbh[1]);
                mma16816(S[2*g+1], qfh[s], kbh[2], kbh[3]);
                mma16816(S[2*g],   qfl[s], kbh[0], kbh[1]);
                mma16816(S[2*g+1], qfl[s], kbh[2], kbh[3]);
                mma16816(S[2*g],   qfh[s], kbl[0], kbl[1]);
                mma16816(S[2*g+1], qfh[s], kbl[2], kbl[3]);
            }
        }
        // mask + scale, store, and accumulate online softmax stats
#pragma unroll
        for(int nt=0;nt<8;nt++){
            int c0=kc*64+nt*8+((lane&3)<<1), c1=c0+1;
            bool b0=(c0<lim1)||(c0>=36&&c0<lim2)||(c0>=KKm);
            bool b1=(c1<lim1)||(c1>=36&&c1<lim2)||(c1>=KKm);
            S[nt][0]=(b0||(sumlo&&c0<MMm))?NEG_INF_F:S[nt][0]*0.125f;
            S[nt][1]=(b1||(sumlo&&c1<MMm))?NEG_INF_F:S[nt][1]*0.125f;
            S[nt][2]=(b0||(sumhi&&c0<MMm))?NEG_INF_F:S[nt][2]*0.125f;
            S[nt][3]=(b1||(sumhi&&c1<MMm))?NEG_INF_F:S[nt][3]*0.125f;
            *(float2*)(rowlo+c0)=make_float2(S[nt][0],S[nt][1]);
            *(float2*)(rowhi+c0)=make_float2(S[nt][2],S[nt][3]);
        }
        float cml=-3e38f, cmh=-3e38f;
#pragma unroll
        for(int nt=0;nt<8;nt++){
            cml=fmaxf(cml,fmaxf(S[nt][0],S[nt][1]));
            cmh=fmaxf(cmh,fmaxf(S[nt][2],S[nt][3]));
        }
        cml=fmaxf(cml,__shfl_xor_sync(0xffffffffu,cml,1));
        cml=fmaxf(cml,__shfl_xor_sync(0xffffffffu,cml,2));
        cmh=fmaxf(cmh,__shfl_xor_sync(0xffffffffu,cmh,1));
        cmh=fmaxf(cmh,__shfl_xor_sync(0xffffffffu,cmh,2));
        float nml=fmaxf(mlo,cml), nmh=fmaxf(mhi,cmh);
        llo*=__expf(mlo-nml); lhi*=__expf(mhi-nmh);
        mlo=nml; mhi=nmh;
        float sl=0.f, sh2=0.f;
#pragma unroll
        for(int nt=0;nt<8;nt++){
            sl +=__expf(S[nt][0]-mlo)+__expf(S[nt][1]-mlo);
            sh2+=__expf(S[nt][2]-mhi)+__expf(S[nt][3]-mhi);
        }
        sl +=__shfl_xor_sync(0xffffffffu,sl,1);
        sl +=__shfl_xor_sync(0xffffffffu,sl,2);
        sh2+=__shfl_xor_sync(0xffffffffu,sh2,1);
        sh2+=__shfl_xor_sync(0xffffffffu,sh2,2);
        llo+=sl; lhi+=sh2;
    }
    // pass 2: re-read own (L2-hot) scores, write normalized pre-split P
    const float ilo=1.f/llo, ihi=1.f/lhi;
    uint32_t* phlo=(uint32_t*)(g_ph+((size_t)bh*192+rlo)*448);
    uint32_t* pllo=(uint32_t*)(g_pl+((size_t)bh*192+rlo)*448);
    uint32_t* phhi=(uint32_t*)(g_ph+((size_t)bh*192+rhi)*448);
    uint32_t* plhi=(uint32_t*)(g_pl+((size_t)bh*192+rhi)*448);
#pragma unroll 1
    for(int kc=0;kc<7;kc++){
#pragma unroll
        for(int nt=0;nt<8;nt++){
            int c0=kc*64+nt*8+((lane&3)<<1);
            float2 a=*(const float2*)(rowlo+c0);
            float2 b=*(const float2*)(rowhi+c0);
            uint32_t hi,lo;
            split_pack(__expf(a.x-mlo)*ilo, __expf(a.y-mlo)*ilo, hi, lo);
            phlo[c0>>1]=hi; pllo[c0>>1]=lo;
            split_pack(__expf(b.x-mhi)*ihi, __expf(b.y-mhi)*ihi, hi, lo);
            phhi[c0>>1]=hi; plhi[c0>>1]=lo;
        }
    }
}

// P @ V: P staged via plain cp.async from pre-split buffers.
__global__ void __launch_bounds__(128) k_pv(){
    __shared__ __align__(16) char sm[4*FTILE];
    const int tid=threadIdx.x, wid=tid>>5, lane=tid&31;
    const int qt=blockIdx.x, bh=blockIdx.y;
    const size_t headoff=(size_t)bh*64;
    const uint32_t spb=smem_u32(sm), svb=spb+2*FTILE;
    const int r=tid>>1, hf=tid&1;
    float out[8][4];
#pragma unroll
    for(int i=0;i<8;i++){out[i][0]=0.f;out[i][1]=0.f;out[i][2]=0.f;out[i][3]=0.f;}
#pragma unroll 1
    for(int kc=0;kc<7;kc++){
        __syncthreads();
        {
            int t=min(kc*64+r,KKm-1);
            const bf16 *vh_=g_vh+(size_t)t*BD+headoff+hf*32, *vl_=g_vl+(size_t)t*BD+headoff+hf*32;
            const bf16 *ph_=g_ph+((size_t)bh*192+qt*64+r)*448+kc*64+hf*32;
            const bf16 *pl2_=g_pl+((size_t)bh*192+qt*64+r)*448+kc*64+hf*32;
            uint32_t dv=svb+(uint32_t)r*FROWB+hf*64;
            uint32_t dp=spb+(uint32_t)r*FROWB+hf*64;
#pragma unroll
            for(int i=0;i<4;i++){
                cp16(dv+i*16, vh_+i*8); cp16(dv+FTILE+i*16, vl_+i*8);
                cp16(dp+i*16, ph_+i*8); cp16(dp+FTILE+i*16, pl2_+i*8);
            }
            asm volatile("cp.async.commit_group;":::"memory");
            asm volatile("cp.async.wait_group 0;":::"memory");
            __syncthreads();
        }
        uint32_t pa=spb+(uint32_t)(wid*16+(lane&15))*FROWB+((lane>>4)<<4);
#pragma unroll
        for(int s=0;s<4;s++){
            uint32_t ph[4], pl_[4];
            ldsm4(ph, pa+s*32);
            ldsm4(pl_, pa+FTILE+s*32);
#pragma unroll
            for(int j=0;j<4;j++){
                uint32_t va=svb+(uint32_t)(s*16+(lane&15))*FROWB+(uint32_t)(j*32+((lane>>4)<<4));
                uint32_t vh4[4], vl4[4];
                ldsm4t(vh4, va);
                ldsm4t(vl4, va+FTILE);
                mma16816(out[2*j],   ph,  vh4[0], vh4[1]);
                mma16816(out[2*j+1], ph,  vh4[2], vh4[3]);
                mma16816(out[2*j],   pl_, vh4[0], vh4[1]);
                mma16816(out[2*j+1], pl_, vh4[2], vh4[3]);
                mma16816(out[2*j],   ph,  vl4[0], vl4[1]);
                mma16816(out[2*j+1], ph,  vl4[2], vl4[3]);
            }
        }
    }
    int glo=qt*64+wid*16+(lane>>2), ghi=glo+8;
#pragma unroll
    for(int nt=0;nt<8;nt++){
        int d=nt*8+((lane&3)<<1);
        if(glo<QQm){
            uint32_t hi,lo;
            split_pack(out[nt][0], out[nt][1], hi, lo);
            *(uint32_t*)(g_ah+(size_t)glo*BD+headoff+d)=hi;
            *(uint32_t*)(g_al+(size_t)glo*BD+headoff+d)=lo;
        }
        if(ghi<QQm){
            uint32_t hi,lo;
            split_pack(out[nt][2], out[nt][3], hi, lo);
            *(uint32_t*)(g_ah+(size_t)ghi*BD+headoff+d)=hi;
            *(uint32_t*)(g_al+(size_t)ghi*BD+headoff+d)=lo;
        }
    }
}

// ---- fp32 -> (hi,lo) bf16 split ----
__device__ __forceinline__ void split4(float4 v, bf162* hp, bf162* lp, size_t i2){
    bf16 h0=__float2bfloat16(v.x), h1=__float2bfloat16(v.y);
    bf16 h2=__float2bfloat16(v.z), h3=__float2bfloat16(v.w);
    hp[i2]=__halves2bfloat162(h0,h1); hp[i2+1]=__halves2bfloat162(h2,h3);
    lp[i2]=__halves2bfloat162(__float2bfloat16(v.x-__bfloat162float(h0)),__float2bfloat16(v.y-__bfloat162float(h1)));
    lp[i2+1]=__halves2bfloat162(__float2bfloat16(v.z-__bfloat162float(h2)),__float2bfloat16(v.w-__bfloat162float(h3)));
}
__global__ void k_split(const float* __restrict__ s, bf16* __restrict__ h, bf16* __restrict__ l){
    size_t i=(size_t)blockIdx.x*blockDim.x+threadIdx.x;
    split4(((const float4*)s)[i], (bf162*)h, (bf162*)l, 2*i);
}
__global__ void k_split_mir(const float* __restrict__ s, bf16* __restrict__ h, bf16* __restrict__ l,
                            float* __restrict__ mir){
    size_t i=(size_t)blockIdx.x*blockDim.x+threadIdx.x;
    float4 v=((const float4*)s)[i];
    split4(v, (bf162*)h, (bf162*)l, 2*i);
    size_t half=(size_t)128*BD/4;
    if(i>=half) ((float4*)mir)[i-half]=v;
}

__device__ __forceinline__ float bsum(float v, float* sh){
    int lane=threadIdx.x&31, w=threadIdx.x>>5;
#pragma unroll
    for(int o=16;o;o>>=1) v+=__shfl_xor_sync(0xffffffffu,v,o);
    if(lane==0) sh[w]=v;
    __syncthreads();
    if(w==0){ float r=(lane<8)?sh[lane]:0.f;
#pragma unroll
        for(int o=4;o;o>>=1) r+=__shfl_xor_sync(0xffffffffu,r,o);
        if(lane==0) sh[0]=r; }
    __syncthreads(); float o=sh[0]; __syncthreads(); return o;
}
__device__ __forceinline__ float4 ln_core(float4 x, const float* gw, const float* bw, int tid, float* sh){
    float mu=bsum(x.x+x.y+x.z+x.w,sh)*(1.f/Dm);
    float d0=x.x-mu,d1=x.y-mu,d2=x.z-mu,d3=x.w-mu;
    float var=bsum(d0*d0+d1*d1+d2*d2+d3*d3,sh)*(1.f/Dm);
    float inv=rsqrtf(var+EPS_LN);
    float4 g4=((const float4*)gw)[tid], b4=((const float4*)bw)[tid];
    return make_float4(d0*inv*g4.x+b4.x, d1*inv*g4.y+b4.y, d2*inv*g4.z+b4.z, d3*inv*g4.w+b4.w);
}
__global__ void __launch_bounds__(256) k_ln_in(const float* __restrict__ rc, const float* __restrict__ utt,
                                               const float* __restrict__ gw, const float* __restrict__ bw){
    __shared__ float sh[8];
    int row=blockIdx.x, tid=threadIdx.x;
    const float* src=(row<RRm*BBm)?rc+(size_t)row*Dm:utt+(size_t)(row-RRm*BBm)*Dm;
    float4 o=ln_core(((const float4*)src)[tid],gw,bw,tid,sh);
    size_t base=(size_t)(4*BBm+row)*Dm;
    ((float4*)(g_cat+base))[tid]=o;
    split4(o,(bf162*)(g_cat_h+base),(bf162*)(g_cat_l+base),2*(size_t)tid);
}
__global__ void __launch_bounds__(256) k_ln_ff(const float* __restrict__ gw, const float* __restrict__ bw){
    __shared__ float sh[8];
    int row=blockIdx.x, tid=threadIdx.x;
    size_t base=(size_t)row*Dm;
    float4 o=ln_core(((const float4*)(g_res+base))[tid],gw,bw,tid,sh);
    split4(o,(bf162*)(g_ffin_h+base),(bf162*)(g_ffin_l+base),2*(size_t)tid);
}
__global__ void __launch_bounds__(256) k_ln_final(const float* __restrict__ gw, const float* __restrict__ bw,
                                                  float* __restrict__ dout){
    __shared__ float sh[8];
    int row=blockIdx.x, tid=threadIdx.x;
    float4 a=((const float4*)(g_res+(size_t)row*Dm))[tid];
    float4 f=((const float4*)(g_ff2+(size_t)row*Dm))[tid];
    float4 g=((const float4*)(g_ff2b+(size_t)row*Dm))[tid];
    float4 o=ln_core(make_float4(a.x+f.x+g.x,a.y+f.y+g.y,a.z+f.z+g.z,a.w+f.w+g.w),gw,bw,tid,sh);
    float* dst=(row<RRm*BBm)?dout+S1_OFF+(size_t)row*Dm:dout+S0_OFF+(size_t)(row-RRm*BBm)*Dm;
    ((float4*)dst)[tid]=o;
}
__global__ void k_summary(){
    int e=blockIdx.x*blockDim.x+threadIdx.x;
    float s=0.f;
#pragma unroll 8
    for(int t=0;t<UUm;t++) s+=g_cat[(size_t)(36+t)*BD+e];
    float v=s*(1.f/SEGm);
    size_t o=(size_t)164*BD+e;
    bf16 h=__float2bfloat16(v);
    g_cat_h[o]=h; g_cat_l[o]=__float2bfloat16(v-__bfloat162float(h));
}

extern "C" void kernel_launch(void* const* d_in, const int* in_sizes, int n_in,
                              void* d_out_v, int out_size) {
    const float* utterance=(const float*)d_in[0];
    const float* right_ctx=(const float*)d_in[1];
    const float* mems_in=(const float*)d_in[2];
    const float* state_mems=(const float*)d_in[3];
    const float* lc_key=(const float*)d_in[4];
    const float* lc_val=(const float*)d_in[5];
    const float* W_kv=(const float*)d_in[6];
    const float* b_kv=(const float*)d_in[7];
    const float* W_q=(const float*)d_in[8];
    const float* b_q=(const float*)d_in[9];
    const float* W_out=(const float*)d_in[10];
    const float* b_out=(const float*)d_in[11];
    const float* ln_in_g=(const float*)d_in[12];
    const float* ln_in_b=(const float*)d_in[13];
    const float* ln_ff_g=(const float*)d_in[14];
    const float* ln_ff_b=(const float*)d_in[15];
    const float* W_ff1=(const float*)d_in[16];
    const float* b_ff1=(const float*)d_in[17];
    const float* W_ff2=(const float*)d_in[18];
    const float* b_ff2=(const float*)d_in[19];
    const float* ln_out_g=(const float*)d_in[20];
    const float* ln_out_b=(const float*)d_in[21];
    const int* past_len=(const int*)d_in[22];
    float* dout=(float*)d_out_v;

    float *res,*ff2b_,*ff2c;
    bf16 *cath,*catl,*qh,*ql,*kh,*kl,*vh,*vl,*ah,*al;
    bf16 *ffinh,*ffinl,*ffhh,*ffhl;
    bf16 *wqh,*wql,*wkvh,*wkvl,*woh,*wol,*w1h,*w1l,*w2h,*w2l;
    cudaGetSymbolAddress((void**)&res,g_res);
    cudaGetSymbolAddress((void**)&ff2b_,g_ff2);
    cudaGetSymbolAddress((void**)&ff2c,g_ff2b);
    cudaGetSymbolAddress((void**)&cath,g_cat_h); cudaGetSymbolAddress((void**)&catl,g_cat_l);
    cudaGetSymbolAddress((void**)&qh,g_qh); cudaGetSymbolAddress((void**)&ql,g_ql);
    cudaGetSymbolAddress((void**)&kh,g_kh); cudaGetSymbolAddress((void**)&kl,g_kl);
    cudaGetSymbolAddress((void**)&vh,g_vh); cudaGetSymbolAddress((void**)&vl,g_vl);
    cudaGetSymbolAddress((void**)&ah,g_ah); cudaGetSymbolAddress((void**)&al,g_al);
    cudaGetSymbolAddress((void**)&ffinh,g_ffin_h); cudaGetSymbolAddress((void**)&ffinl,g_ffin_l);
    cudaGetSymbolAddress((void**)&ffhh,g_ffh_h); cudaGetSymbolAddress((void**)&ffhl,g_ffh_l);
    cudaGetSymbolAddress((void**)&wqh,g_wq_h); cudaGetSymbolAddress((void**)&wql,g_wq_l);
    cudaGetSymbolAddress((void**)&wkvh,g_wkv_h); cudaGetSymbolAddress((void**)&wkvl,g_wkv_l);
    cudaGetSymbolAddress((void**)&woh,g_wo_h); cudaGetSymbolAddress((void**)&wol,g_wo_l);
    cudaGetSymbolAddress((void**)&w1h,g_w1_h); cudaGetSymbolAddress((void**)&w1l,g_w1_l);
    cudaGetSymbolAddress((void**)&w2h,g_w2_h); cudaGetSymbolAddress((void**)&w2l,g_w2_l);

    cudaFuncSetAttribute(gemm_mma, cudaFuncAttributeMaxDynamicSharedMemorySize, GEMM_SMEM);
    cudaFuncSetAttribute(gemm_qkv, cudaFuncAttributeMaxDynamicSharedMemorySize, GEMM_SMEM);

    k_split<<<(4*BD/4)/256,256>>>(state_mems, cath, catl);
    k_split<<<(Dm*Dm/4)/256,256>>>(W_q, wqh, wql);
    k_ln_in<<<TTm*BBm,256>>>(right_ctx, utterance, ln_in_g, ln_in_b);
    k_summary<<<BD/256,256>>>();
    k_split<<<(2*Dm*Dm/4)/256,256>>>(W_kv, wkvh, wkvl);
    // merged Q + KV projection
    gemm_qkv<<<QBLK+16*82,256,GEMM_SMEM>>>(cath, catl,
        wqh, wql, b_q, qh, ql,
        wkvh, wkvl, b_kv, kh, kl, vh, vl,
        dout+S4_OFF+(size_t)128*BD, dout+S5_OFF+(size_t)128*BD);
    // cached local-context K/V -> split middles + fp32 mirror to dout
    k_split_mir<<<((size_t)LLm*BD/4)/256,256>>>(lc_key, kh+(size_t)36*BD, kl+(size_t)36*BD, dout+S4_OFF);
    k_split_mir<<<((size_t)LLm*BD/4)/256,256>>>(lc_val, vh+(size_t)36*BD, vl+(size_t)36*BD, dout+S5_OFF);
    // attention: QK^T with fused softmax (writes pre-split P), then PV
    k_qk<<<dim3(3,1024),128>>>(past_len);
    k_pv<<<dim3(3,1024),128>>>();
    k_split<<<(Dm*Dm/4)/256,256>>>(W_out, woh, wol);
    // W_out projection with fused residual + clip (mode 3)
    gemm_mma<<<dim3(8,81),256,GEMM_SMEM>>>(ah, al, Dm, woh, wol, Dm,
        b_out, QQm*BBm, Dm, 3, res, nullptr, nullptr, Dm, nullptr, nullptr,
        (float*)right_ctx, (float*)utterance, dout+S2_OFF);
    // FFN
    k_ln_ff<<<TTm*BBm,256>>>(ln_ff_g, ln_ff_b);
    k_split<<<((size_t)FFNm*Dm/4)/256,256>>>(W_ff1, w1h, w1l);
    gemm_mma<<<dim3(32,80),256,GEMM_SMEM>>>(ffinh, ffinl, Dm, w1h, w1l, Dm,
        b_ff1, TTm*BBm, Dm, 1, nullptr, ffhh, ffhl, FFNm, nullptr, nullptr, nullptr, nullptr, nullptr);
    k_split<<<((size_t)FFNm*Dm/4)/256,256>>>(W_ff2, w2h, w2l);
    // FF2 split-K x2
    gemm_mma<<<dim3(8,80,2),256,GEMM_SMEM>>>(ffhh, ffhl, FFNm, w2h, w2l, FFNm,
        b_ff2, TTm*BBm, 2048, 0, ff2b_, nullptr, nullptr, Dm, nullptr, nullptr,
        nullptr, nullptr, ff2c);
    k_ln_final<<<TTm*BBm,256>>>(ln_out_g, ln_out_b, dout);
    // state-carry
    cudaMemcpyAsync(dout+S3_OFF, state_mems+BD, (size_t)3*BD*sizeof(float), cudaMemcpyDeviceToDevice, 0);
    cudaMemcpyAsync(dout+S3_OFF+(size_t)3*BD, mems_in, (size_t)BD*sizeof(float), cudaMemcpyDeviceToDevice, 0);
}

// round 17
// speedup vs baseline: 1.0612x; 1.0165x over previous
#include <cuda_runtime.h>
#include <cuda_bf16.h>
#include <cstdint>
#include <cstddef>

#define Dm 1024
#define FFNm 4096
#define SEGm 128
#define LLm 256
#define MMm 4
#define BBm 64
#define UUm 128
#define RRm 32
#define TTm 160
#define QQm 161
#define KKm 420
#define BD (BBm*Dm)
#define NEG_INF_F (-1e8f)
#define EPS_LN 1e-5f
#define S0_OFF 0u
#define S1_OFF 8388608u
#define S2_OFF 10485760u
#define S3_OFF 10551296u
#define S4_OFF 10813440u
#define S5_OFF 27590656u

typedef __nv_bfloat16 bf16;
typedef __nv_bfloat162 bf162;

__device__ float g_cat[165*BD];
__device__ float g_res[TTm*BD];
__device__ float g_ff2[TTm*BD];
__device__ float g_ff2b[TTm*BD];
__device__ float g_scores[(size_t)1024*192*448];
__device__ bf16 g_cat_h[165*BD], g_cat_l[165*BD];
__device__ bf16 g_qh[QQm*BD], g_ql[QQm*BD];
__device__ bf16 g_kh[448*BD], g_kl[448*BD];
__device__ bf16 g_vh[448*BD], g_vl[448*BD];
__device__ bf16 g_ah[QQm*BD], g_al[QQm*BD];
__device__ bf16 g_ffin_h[TTm*BD], g_ffin_l[TTm*BD];
__device__ bf16 g_ffh_h[(size_t)TTm*BBm*FFNm], g_ffh_l[(size_t)TTm*BBm*FFNm];
__device__ bf16 g_wq_h[Dm*Dm], g_wq_l[Dm*Dm];
__device__ bf16 g_wkv_h[2*Dm*Dm], g_wkv_l[2*Dm*Dm];
__device__ bf16 g_wo_h[Dm*Dm], g_wo_l[Dm*Dm];
__device__ bf16 g_w1_h[FFNm*Dm], g_w1_l[FFNm*Dm];
__device__ bf16 g_w2_h[Dm*FFNm], g_w2_l[Dm*FFNm];

__device__ __forceinline__ uint32_t smem_u32(const void* p){
    uint32_t a; asm("{ .reg .u64 t; cvta.to.shared.u64 t, %1; cvt.u32.u64 %0, t; }":"=r"(a):"l"(p)); return a;
}
__device__ __forceinline__ void cp16(uint32_t dst, const void* src){
    asm volatile("cp.async.cg.shared.global [%0], [%1], 16;"::"r"(dst),"l"(src));
}
__device__ __forceinline__ void ldsm4(uint32_t* r, uint32_t addr){
    asm volatile("ldmatrix.sync.aligned.m8n8.x4.shared.b16 {%0,%1,%2,%3}, [%4];"
        :"=r"(r[0]),"=r"(r[1]),"=r"(r[2]),"=r"(r[3]):"r"(addr));
}
__device__ __forceinline__ void ldsm4t(uint32_t* r, uint32_t addr){
    asm volatile("ldmatrix.sync.aligned.m8n8.x4.trans.shared.b16 {%0,%1,%2,%3}, [%4];"
        :"=r"(r[0]),"=r"(r[1]),"=r"(r[2]),"=r"(r[3]):"r"(addr));
}
__device__ __forceinline__ void mma16816(float* c, const uint32_t* a, uint32_t b0, uint32_t b1){
    asm volatile("mma.sync.aligned.m16n8k16.row.col.f32.bf16.bf16.f32 "
        "{%0,%1,%2,%3}, {%4,%5,%6,%7}, {%8,%9}, {%0,%1,%2,%3};"
        :"+f"(c[0]),"+f"(c[1]),"+f"(c[2]),"+f"(c[3])
        :"r"(a[0]),"r"(a[1]),"r"(a[2]),"r"(a[3]),"r"(b0),"r"(b1));
}
__device__ __forceinline__ void split_pack(float a, float b, uint32_t& hi, uint32_t& lo){
    bf16 ha=__float2bfloat16(a), hb=__float2bfloat16(b);
    hi=(uint32_t)__bfloat16_as_ushort(ha)|((uint32_t)__bfloat16_as_ushort(hb)<<16);
    bf16 la=__float2bfloat16(a-__bfloat162float(ha)), lb=__float2bfloat16(b-__bfloat162float(hb));
    lo=(uint32_t)__bfloat16_as_ushort(la)|((uint32_t)__bfloat16_as_ushort(lb)<<16);
}

// ---- HMMA split-bf16 GEMM body (tile 128x128, BK=32, fused 3-pass, 2-stage) ----
#define ROWB 80
#define TILEB 10240
#define STAGEB 40960
#define GEMM_SMEM (2*STAGEB)
__device__ __noinline__ void gemm_body(
    int bx, int by, int bz,
    const bf16* Ah_, const bf16* Al_, int lda,
    const bf16* Bh_, const bf16* Bl_, int ldb,
    const float* bias, int M, int K, int mode,
    float* F0, bf16* H0, bf16* L0, int ldc,
    bf16* H1, bf16* L1,
    float* F1, float* F2, float* F3)
{
    extern __shared__ __align__(16) char smem[];
    const int tid=threadIdx.x, wid=tid>>5, lane=tid&31;
    const int m0=by*128, n0=bx*128;
    const int m0w=(wid>>1)*32, n0w=(wid&1)*64;
    const uint32_t sb=smem_u32(smem);
    const int nIt=K>>5;
    const int kbase=bz*K;
    Ah_+=kbase; Al_+=kbase; Bh_+=kbase; Bl_+=kbase;
    if(bz==1){ F0=F3; bias=nullptr; }

    float acc[2][8][4];
#pragma unroll
    for(int i=0;i<2;i++)
#pragma unroll
        for(int j=0;j<8;j++)
#pragma unroll
            for(int l=0;l<4;l++) acc[i][j][l]=0.f;

    const int lrow=tid>>1, le0=(tid&1)*16;
    int gra=m0+lrow; if(gra>=M) gra=M-1;
    const int grb=n0+lrow;

    auto load_stage=[&](int it){
        int kk=it<<5;
        uint32_t st=sb+(it&1)*STAGEB;
        uint32_t rb=st+(uint32_t)lrow*ROWB+le0*2;
        cp16(rb,          Ah_+(size_t)gra*lda+kk+le0);
        cp16(rb+16,       Ah_+(size_t)gra*lda+kk+le0+8);
        cp16(rb+TILEB,    Al_+(size_t)gra*lda+kk+le0);
        cp16(rb+TILEB+16, Al_+(size_t)gra*lda+kk+le0+8);
        cp16(rb+2*TILEB,    Bh_+(size_t)grb*ldb+kk+le0);
        cp16(rb+2*TILEB+16, Bh_+(size_t)grb*ldb+kk+le0+8);
        cp16(rb+3*TILEB,    Bl_+(size_t)grb*ldb+kk+le0);
        cp16(rb+3*TILEB+16, Bl_+(size_t)grb*ldb+kk+le0+8);
        asm volatile("cp.async.commit_group;":::"memory");
    };

    load_stage(0); load_stage(1);
    for(int it=0; it<nIt; ++it){
        asm volatile("cp.async.wait_group 1;":::"memory");
        __syncthreads();
        uint32_t st=sb+(it&1)*STAGEB;
        uint32_t aoff=st+(uint32_t)(m0w+(lane&15))*ROWB+((lane>>4)<<4);
        uint32_t boff=st+2*TILEB+(uint32_t)(n0w+(lane&7)+((lane>>4)<<3))*ROWB+(((lane>>3)&1)<<4);
#pragma unroll
        for(int ks=0;ks<2;++ks){
            uint32_t af[4][4], bb[4][4];
            ldsm4(af[0], aoff+ks*32);
            ldsm4(af[1], aoff+16*ROWB+ks*32);
            ldsm4(af[2], aoff+TILEB+ks*32);
            ldsm4(af[3], aoff+TILEB+16*ROWB+ks*32);
#pragma unroll
            for(int np=0;np<4;++np) ldsm4(bb[np], boff+np*16*ROWB+ks*32);
#pragma unroll
            for(int mt=0;mt<2;++mt)
#pragma unroll
                for(int nt=0;nt<8;++nt){
                    int p=nt>>1,h=(nt&1)<<1;
                    mma16816(acc[mt][nt], af[mt],   bb[p][h], bb[p][h+1]);
                    mma16816(acc[mt][nt], af[2+mt], bb[p][h], bb[p][h+1]);
                }
#pragma unroll
            for(int np=0;np<4;++np) ldsm4(bb[np], boff+TILEB+np*16*ROWB+ks*32);
#pragma unroll
            for(int mt=0;mt<2;++mt)
#pragma unroll
                for(int nt=0;nt<8;++nt){
                    int p=nt>>1,h=(nt&1)<<1;
                    mma16816(acc[mt][nt], af[mt], bb[p][h], bb[p][h+1]);
                }
        }
        __syncthreads();
        if(it+2<nIt) load_stage(it+2);
    }

#pragma unroll
    for(int mt=0;mt<2;++mt){
        int rr=m0+m0w+mt*16+(lane>>2);
#pragma unroll
        for(int nt=0;nt<8;++nt){
            int c=n0+n0w+nt*8+((lane&3)<<1);
            float b0=bias?__ldg(bias+c):0.f, b1=bias?__ldg(bias+c+1):0.f;
#pragma unroll
            for(int hr=0;hr<2;++hr){
                int r=rr+hr*8;
                if(r>=M) continue;
                float v0=acc[mt][nt][hr*2]+b0, v1=acc[mt][nt][hr*2+1]+b1;
                if(mode==0){
                    *(float2*)(F0+(size_t)r*ldc+c)=make_float2(v0,v1);
                } else if(mode==1||mode==4){
                    if(mode==1){v0=fmaxf(v0,0.f);v1=fmaxf(v1,0.f);}
                    uint32_t hi,lo; split_pack(v0,v1,hi,lo);
                    *(uint32_t*)(H0+(size_t)r*ldc+c)=hi;
                    *(uint32_t*)(L0+(size_t)r*ldc+c)=lo;
                } else if(mode==2){
                    int rk=r+(r>=2304?16384:0);
                    uint32_t hi,lo; split_pack(v0,v1,hi,lo);
                    if(c<1024){
                        *(uint32_t*)(H0+(size_t)rk*1024+c)=hi;
                        *(uint32_t*)(L0+(size_t)rk*1024+c)=lo;
                        if(r>=2304) *(float2*)(F1+(size_t)(r-2304)*1024+c)=make_float2(v0,v1);
                    } else {
                        int cc=c-1024;
                        *(uint32_t*)(H1+(size_t)rk*1024+cc)=hi;
                        *(uint32_t*)(L1+(size_t)rk*1024+cc)=lo;
                        if(r>=2304) *(float2*)(F2+(size_t)(r-2304)*1024+cc)=make_float2(v0,v1);
                    }
                } else {
                    if(r<10240){
                        const float* resid=(r<2048)?F1+(size_t)r*1024+c:F2+(size_t)(r-2048)*1024+c;
                        float2 rv=*(const float2*)resid;
                        *(float2*)(F0+(size_t)r*1024+c)=make_float2(v0+rv.x,v1+rv.y);
                    } else {
                        v0=fminf(fmaxf(v0,-10.f),10.f); v1=fminf(fmaxf(v1,-10.f),10.f);
                        *(float2*)(F3+(size_t)(r-10240)*1024+c)=make_float2(v0,v1);
                    }
                }
            }
        }
    }
}

__global__ void __launch_bounds__(256,2) gemm_mma(
    const bf16* __restrict__ Ah_, const bf16* __restrict__ Al_, int lda,
    const bf16* __restrict__ Bh_, const bf16* __restrict__ Bl_, int ldb,
    const float* __restrict__ bias, int M, int K, int mode,
    float* __restrict__ F0, bf16* __restrict__ H0, bf16* __restrict__ L0, int ldc,
    bf16* __restrict__ H1, bf16* __restrict__ L1,
    float* __restrict__ F1, float* __restrict__ F2, float* __restrict__ F3)
{
    gemm_body(blockIdx.x, blockIdx.y, blockIdx.z, Ah_, Al_, lda, Bh_, Bl_, ldb,
              bias, M, K, mode, F0, H0, L0, ldc, H1, L1, F1, F2, F3);
}

#define QBLK 648
__global__ void __launch_bounds__(256,2) gemm_qkv(
    const bf16* __restrict__ cath, const bf16* __restrict__ catl,
    const bf16* __restrict__ wqh, const bf16* __restrict__ wql,
    const float* __restrict__ b_q, bf16* __restrict__ qh, bf16* __restrict__ ql,
    const bf16* __restrict__ wkvh, const bf16* __restrict__ wkvl,
    const float* __restrict__ b_kv, bf16* __restrict__ kh, bf16* __restrict__ kl,
    bf16* __restrict__ vh, bf16* __restrict__ vl,
    float* __restrict__ km, float* __restrict__ vm)
{
    int id=blockIdx.x;
    if(id<QBLK){
        gemm_body(id&7, id>>3, 0, cath+(size_t)4*BD, catl+(size_t)4*BD, Dm, wqh, wql, Dm,
                  b_q, QQm*BBm, Dm, 4, nullptr, qh, ql, Dm,
                  nullptr, nullptr, nullptr, nullptr, nullptr);
    } else {
        id-=QBLK;
        gemm_body(id&15, id>>4, 0, cath, catl, Dm, wkvh, wkvl, Dm,
                  b_kv, 164*BBm, Dm, 2, nullptr, kh, kl, 0,
                  vh, vl, km, vm, nullptr);
    }
}

// ---- attention kernels (R13 best config, untouched) ----
#define FROWB 144
#define FTILE 9216

__global__ void __launch_bounds__(128) k_qk(const int* __restrict__ past_len){
    __shared__ __align__(16) char sm[4*FTILE];
    const int tid=threadIdx.x, wid=tid>>5, lane=tid&31;
    const int qt=blockIdx.x, bh=blockIdx.y;
    const size_t headoff=(size_t)bh*64;
    const uint32_t sqb=smem_u32(sm), skb=sqb+2*FTILE;
    const int pl=past_len[0], m_kv=min(LLm,pl), m_m=min(MMm,pl/SEGm);
    const int lim1=MMm-m_m, lim2=36+(LLm-m_kv);
    const int r=tid>>1, hf=tid&1;
    {
        int gq=min(qt*64+r,160);
        const bf16* sh_=g_qh+(size_t)gq*BD+headoff+hf*32;
        const bf16* sl_=g_ql+(size_t)gq*BD+headoff+hf*32;
        uint32_t d0=sqb+(uint32_t)r*FROWB+hf*64;
#pragma unroll
        for(int i=0;i<4;i++){ cp16(d0+i*16, sh_+i*8); cp16(d0+FTILE+i*16, sl_+i*8); }
        asm volatile("cp.async.commit_group;":::"memory");
        asm volatile("cp.async.wait_group 0;":::"memory");
        __syncthreads();
    }
    uint32_t qfh[4][4], qfl[4][4];
    {
        uint32_t qa=sqb+(uint32_t)(wid*16+(lane&15))*FROWB+((lane>>4)<<4);
#pragma unroll
        for(int s=0;s<4;s++){ ldsm4(qfh[s], qa+s*32); ldsm4(qfl[s], qa+FTILE+s*32); }
    }
    const int rlo=qt*64+wid*16+(lane>>2), rhi=rlo+8;
    const bool sumlo=(rlo==160), sumhi=(rhi==160);
    float* rowlo=g_scores+((size_t)bh*192+rlo)*448;
    float* rowhi=g_scores+((size_t)bh*192+rhi)*448;
#pragma unroll 1
    for(int kc=0;kc<7;kc++){
        __syncthreads();
        {
            int t=min(kc*64+r,KKm-1);
            const bf16 *kh_=g_kh+(size_t)t*BD+headoff+hf*32, *kl_=g_kl+(size_t)t*BD+headoff+hf*32;
            uint32_t dk=skb+(uint32_t)r*FROWB+hf*64;
#pragma unroll
            for(int i=0;i<4;i++){ cp16(dk+i*16, kh_+i*8); cp16(dk+FTILE+i*16, kl_+i*8); }
            asm volatile("cp.async.commit_group;":::"memory");
            asm volatile("cp.async.wait_group 0;":::"memory");
            __syncthreads();
        }
        float S[8][4];
#pragma unroll
        for(int i=0;i<8;i++){S[i][0]=0.f;S[i][1]=0.f;S[i][2]=0.f;S[i][3]=0.f;}
#pragma unroll
        for(int s=0;s<4;s++){
#pragma unroll
            for(int g=0;g<4;g++){
                uint32_t kaddr=skb+(uint32_t)(g*16+(lane&7)+((lane>>4)<<3))*FROWB+(((lane>>3)&1)<<4)+s*32;
                uint32_t kbh[4], kbl[4];
                ldsm4(kbh, kaddr);
                ldsm4(kbl, kaddr+FTILE);
                mma16816(S[2*g],   qfh[s], kbh[0], kbh[1]);
                mma16816(S[2*g+1], qfh[s], kbh[2], kbh[3]);
                mma16816(S[2*g],   qfl[s], kbh[0], kbh[1]);
                mma16816(S[2*g+1], qfl[s], kbh[2], kbh[3]);
                mma16816(S[2*g],   qfh[s], kbl[0], kbl[1]);
                mma16816(S[2*g+1], qfh[s], kbl[2], kbl[3]);
            }
        }
#pragma unroll
        for(int nt=0;nt<8;nt++){
            int c0=kc*64+nt*8+((lane&3)<<1), c1=c0+1;
            bool b0=(c0<lim1)||(c0>=36&&c0<lim2)||(c0>=KKm);
            bool b1=(c1<lim1)||(c1>=36&&c1<lim2)||(c1>=KKm);
            float s0=(b0||(sumlo&&c0<MMm))?NEG_INF_F:S[nt][0]*0.125f;
            float s1=(b1||(sumlo&&c1<MMm))?NEG_INF_F:S[nt][1]*0.125f;
            float s2=(b0||(sumhi&&c0<MMm))?NEG_INF_F:S[nt][2]*0.125f;
            float s3=(b1||(sumhi&&c1<MMm))?NEG_INF_F:S[nt][3]*0.125f;
            *(float2*)(rowlo+c0)=make_float2(s0,s1);
            *(float2*)(rowhi+c0)=make_float2(s2,s3);
        }
    }
}

__global__ void __launch_bounds__(128) k_softmax2(){
    __shared__ float sred[4];
    float* row=g_scores+(size_t)blockIdx.x*448;
    int tid=threadIdx.x, lane=tid&31, w=tid>>5;
    float v[4], mx=-3.4e38f;
#pragma unroll
    for(int j=0;j<4;j++){
        int c=tid+128*j;
        v[j]=(c<448)?row[c]:-3.4e38f;
        mx=fmaxf(mx,v[j]);
    }
#pragma unroll
    for(int o=16;o;o>>=1) mx=fmaxf(mx,__shfl_xor_sync(0xffffffffu,mx,o));
    if(lane==0) sred[w]=mx;
    __syncthreads();
    mx=fmaxf(fmaxf(sred[0],sred[1]),fmaxf(sred[2],sred[3]));
    __syncthreads();
    float s=0.f;
#pragma unroll
    for(int j=0;j<4;j++){ int c=tid+128*j; if(c<448){ v[j]=__expf(v[j]-mx); s+=v[j]; } }
#pragma unroll
    for(int o=16;o;o>>=1) s+=__shfl_xor_sync(0xffffffffu,s,o);
    if(lane==0) sred[w]=s;
    __syncthreads();
    s=sred[0]+sred[1]+sred[2]+sred[3];
    float r=1.f/s;
#pragma unroll
    for(int j=0;j<4;j++){ int c=tid+128*j; if(c<448) row[c]=v[j]*r; }
}

__global__ void __launch_bounds__(128) k_pv(){
    __shared__ __align__(16) char sm[4*FTILE];
    const int tid=threadIdx.x, wid=tid>>5, lane=tid&31;
    const int qt=blockIdx.x, bh=blockIdx.y;
    const size_t headoff=(size_t)bh*64;
    const uint32_t spb=smem_u32(sm), svb=spb+2*FTILE;
    const int r=tid>>1, hf=tid&1;
    float out[8][4];
#pragma unroll
    for(int i=0;i<8;i++){out[i][0]=0.f;out[i][1]=0.f;out[i][2]=0.f;out[i][3]=0.f;}
#pragma unroll 1
    for(int kc=0;kc<7;kc++){
        __syncthreads();
        {
            int t=min(kc*64+r,KKm-1);
            const bf16 *vh_=g_vh+(size_t)t*BD+headoff+hf*32, *vl_=g_vl+(size_t)t*BD+headoff+hf*32;
            uint32_t dv=svb+(uint32_t)r*FROWB+hf*64;
#pragma unroll
            for(int i=0;i<4;i++){ cp16(dv+i*16, vh_+i*8); cp16(dv+FTILE+i*16, vl_+i*8); }
            asm volatile("cp.async.commit_group;":::"memory");
            const float4* pr=(const float4*)(g_scores+((size_t)bh*192+qt*64+r)*448+kc*64+hf*32);
            char* dp=sm+(size_t)r*FROWB+hf*64;
#pragma unroll
            for(int i2=0;i2<4;i2++){
                float4 a=pr[2*i2], b=pr[2*i2+1];
                uint32_t h0,l0,h1,l1,h2,l2,h3,l3;
                split_pack(a.x,a.y,h0,l0); split_pack(a.z,a.w,h1,l1);
                split_pack(b.x,b.y,h2,l2); split_pack(b.z,b.w,h3,l3);
                *(uint4*)(dp+i2*16)=make_uint4(h0,h1,h2,h3);
                *(uint4*)(dp+FTILE+i2*16)=make_uint4(l0,l1,l2,l3);
            }
            asm volatile("cp.async.wait_group 0;":::"memory");
            __syncthreads();
        }
        uint32_t pa=spb+(uint32_t)(wid*16+(lane&15))*FROWB+((lane>>4)<<4);
#pragma unroll
        for(int s=0;s<4;s++){
            uint32_t ph[4], pl_[4];
            ldsm4(ph, pa+s*32);
            ldsm4(pl_, pa+FTILE+s*32);
#pragma unroll
            for(int j=0;j<4;j++){
                uint32_t va=svb+(uint32_t)(s*16+(lane&15))*FROWB+(uint32_t)(j*32+((lane>>4)<<4));
                uint32_t vh4[4], vl4[4];
                ldsm4t(vh4, va);
                ldsm4t(vl4, va+FTILE);
                mma16816(out[2*j],   ph,  vh4[0], vh4[1]);
                mma16816(out[2*j+1], ph,  vh4[2], vh4[3]);
                mma16816(out[2*j],   pl_, vh4[0], vh4[1]);
                mma16816(out[2*j+1], pl_, vh4[2], vh4[3]);
                mma16816(out[2*j],   ph,  vl4[0], vl4[1]);
                mma16816(out[2*j+1], ph,  vl4[2], vl4[3]);
            }
        }
    }
    int glo=qt*64+wid*16+(lane>>2), ghi=glo+8;
#pragma unroll
    for(int nt=0;nt<8;nt++){
        int d=nt*8+((lane&3)<<1);
        if(glo<QQm){
            uint32_t hi,lo;
            split_pack(out[nt][0], out[nt][1], hi, lo);
            *(uint32_t*)(g_ah+(size_t)glo*BD+headoff+d)=hi;
            *(uint32_t*)(g_al+(size_t)glo*BD+headoff+d)=lo;
        }
        if(ghi<QQm){
            uint32_t hi,lo;
            split_pack(out[nt][2], out[nt][3], hi, lo);
            *(uint32_t*)(g_ah+(size_t)ghi*BD+headoff+d)=hi;
            *(uint32_t*)(g_al+(size_t)ghi*BD+headoff+d)=lo;
        }
    }
}

// ---- fp32 -> (hi,lo) bf16 split helpers ----
__device__ __forceinline__ void split4(float4 v, bf162* hp, bf162* lp, size_t i2){
    bf16 h0=__float2bfloat16(v.x), h1=__float2bfloat16(v.y);
    bf16 h2=__float2bfloat16(v.z), h3=__float2bfloat16(v.w);
    hp[i2]=__halves2bfloat162(h0,h1); hp[i2+1]=__halves2bfloat162(h2,h3);
    lp[i2]=__halves2bfloat162(__float2bfloat16(v.x-__bfloat162float(h0)),__float2bfloat16(v.y-__bfloat162float(h1)));
    lp[i2+1]=__halves2bfloat162(__float2bfloat16(v.z-__bfloat162float(h2)),__float2bfloat16(v.w-__bfloat162float(h3)));
}

// merged split of all weights + state_mems: one launch, one wave tail.
// segments (float4 counts): state_mems 65536 | W_q 262144 | W_kv 524288 | W_out 262144 | W_ff1 1048576 | W_ff2 1048576
#define SPLITALL_BLOCKS 12544
__global__ void __launch_bounds__(256) k_split_all(
    const float* __restrict__ s0, bf16* __restrict__ h0, bf16* __restrict__ l0,
    const float* __restrict__ s1, bf16* __restrict__ h1, bf16* __restrict__ l1,
    const float* __restrict__ s2, bf16* __restrict__ h2, bf16* __restrict__ l2,
    const float* __restrict__ s3, bf16* __restrict__ h3, bf16* __restrict__ l3,
    const float* __restrict__ s4, bf16* __restrict__ h4, bf16* __restrict__ l4,
    const float* __restrict__ s5, bf16* __restrict__ h5, bf16* __restrict__ l5)
{
    size_t i=(size_t)blockIdx.x*256+threadIdx.x;
    const float* s; bf16 *h,*l; size_t off;
    if(i<65536){ s=s0;h=h0;l=l0;off=i; }
    else if(i<327680){ s=s1;h=h1;l=l1;off=i-65536; }
    else if(i<851968){ s=s2;h=h2;l=l2;off=i-327680; }
    else if(i<1114112){ s=s3;h=h3;l=l3;off=i-851968; }
    else if(i<2162688){ s=s4;h=h4;l=l4;off=i-1114112; }
    else { s=s5;h=h5;l=l5;off=i-2162688; }
    split4(((const float4*)s)[off], (bf162*)h, (bf162*)l, 2*off);
}

// merged lc_key + lc_val split with fp32 mirror of rows >= 128 into dout
#define MIR2_BLOCKS 32768
__global__ void __launch_bounds__(256) k_split_mir2(
    const float* __restrict__ ks, const float* __restrict__ vs,
    bf16* __restrict__ kh, bf16* __restrict__ kl,
    bf16* __restrict__ vh, bf16* __restrict__ vl,
    float* __restrict__ km, float* __restrict__ vm)
{
    const size_t n=(size_t)LLm*BD/4;
    size_t i=(size_t)blockIdx.x*256+threadIdx.x;
    const float* s; bf16 *h,*l; float* mir; size_t off;
    if(i<n){ s=ks;h=kh;l=kl;mir=km;off=i; }
    else   { s=vs;h=vh;l=vl;mir=vm;off=i-n; }
    float4 v=((const float4*)s)[off];
    split4(v,(bf162*)h,(bf162*)l,2*off);
    size_t half=(size_t)128*BD/4;
    if(off>=half) ((float4*)mir)[off-half]=v;
}

__device__ __forceinline__ float bsum(float v, float* sh){
    int lane=threadIdx.x&31, w=threadIdx.x>>5;
#pragma unroll
    for(int o=16;o;o>>=1) v+=__shfl_xor_sync(0xffffffffu,v,o);
    if(lane==0) sh[w]=v;
    __syncthreads();
    if(w==0){ float r=(lane<8)?sh[lane]:0.f;
#pragma unroll
        for(int o=4;o;o>>=1) r+=__shfl_xor_sync(0xffffffffu,r,o);
        if(lane==0) sh[0]=r; }
    __syncthreads(); float o=sh[0]; __syncthreads(); return o;
}
__device__ __forceinline__ float4 ln_core(float4 x, const float* gw, const float* bw, int tid, float* sh){
    float mu=bsum(x.x+x.y+x.z+x.w,sh)*(1.f/Dm);
    float d0=x.x-mu,d1=x.y-mu,d2=x.z-mu,d3=x.w-mu;
    float var=bsum(d0*d0+d1*d1+d2*d2+d3*d3,sh)*(1.f/Dm);
    float inv=rsqrtf(var+EPS_LN);
    float4 g4=((const float4*)gw)[tid], b4=((const float4*)bw)[tid];
    return make_float4(d0*inv*g4.x+b4.x, d1*inv*g4.y+b4.y, d2*inv*g4.z+b4.z, d3*inv*g4.w+b4.w);
}
__global__ void __launch_bounds__(256) k_ln_in(const float* __restrict__ rc, const float* __restrict__ utt,
                                               const float* __restrict__ gw, const float* __restrict__ bw){
    __shared__ float sh[8];
    int row=blockIdx.x, tid=threadIdx.x;
    const float* src=(row<RRm*BBm)?rc+(size_t)row*Dm:utt+(size_t)(row-RRm*BBm)*Dm;
    float4 o=ln_core(((const float4*)src)[tid],gw,bw,tid,sh);
    size_t base=(size_t)(4*BBm+row)*Dm;
    ((float4*)(g_cat+base))[tid]=o;
    split4(o,(bf162*)(g_cat_h+base),(bf162*)(g_cat_l+base),2*(size_t)tid);
}
__global__ void __launch_bounds__(256) k_ln_ff(const float* __restrict__ gw, const float* __restrict__ bw){
    __shared__ float sh[8];
    int row=blockIdx.x, tid=threadIdx.x;
    size_t base=(size_t)row*Dm;
    float4 o=ln_core(((const float4*)(g_res+base))[tid],gw,bw,tid,sh);
    split4(o,(bf162*)(g_ffin_h+base),(bf162*)(g_ffin_l+base),2*(size_t)tid);
}
__global__ void __launch_bounds__(256) k_ln_final(const float* __restrict__ gw, const float* __restrict__ bw,
                                                  float* __restrict__ dout){
    __shared__ float sh[8];
    int row=blockIdx.x, tid=threadIdx.x;
    float4 a=((const float4*)(g_res+(size_t)row*Dm))[tid];
    float4 f=((const float4*)(g_ff2+(size_t)row*Dm))[tid];
    float4 g=((const float4*)(g_ff2b+(size_t)row*Dm))[tid];
    float4 o=ln_core(make_float4(a.x+f.x+g.x,a.y+f.y+g.y,a.z+f.z+g.z,a.w+f.w+g.w),gw,bw,tid,sh);
    float* dst=(row<RRm*BBm)?dout+S1_OFF+(size_t)row*Dm:dout+S0_OFF+(size_t)(row-RRm*BBm)*Dm;
    ((float4*)dst)[tid]=o;
}
__global__ void k_summary(){
    int e=blockIdx.x*blockDim.x+threadIdx.x;
    float s=0.f;
#pragma unroll 8
    for(int t=0;t<UUm;t++) s+=g_cat[(size_t)(36+t)*BD+e];
    float v=s*(1.f/SEGm);
    size_t o=(size_t)164*BD+e;
    bf16 h=__float2bfloat16(v);
    g_cat_h[o]=h; g_cat_l[o]=__float2bfloat16(v-__bfloat162float(h));
}

extern "C" void kernel_launch(void* const* d_in, const int* in_sizes, int n_in,
                              void* d_out_v, int out_size) {
    const float* utterance=(const float*)d_in[0];
    const float* right_ctx=(const float*)d_in[1];
    const float* mems_in=(const float*)d_in[2];
    const float* state_mems=(const float*)d_in[3];
    const float* lc_key=(const float*)d_in[4];
    const float* lc_val=(const float*)d_in[5];
    const float* W_kv=(const float*)d_in[6];
    const float* b_kv=(const float*)d_in[7];
    const float* W_q=(const float*)d_in[8];
    const float* b_q=(const float*)d_in[9];
    const float* W_out=(const float*)d_in[10];
    const float* b_out=(const float*)d_in[11];
    const float* ln_in_g=(const float*)d_in[12];
    const float* ln_in_b=(const float*)d_in[13];
    const float* ln_ff_g=(const float*)d_in[14];
    const float* ln_ff_b=(const float*)d_in[15];
    const float* W_ff1=(const float*)d_in[16];
    const float* b_ff1=(const float*)d_in[17];
    const float* W_ff2=(const float*)d_in[18];
    const float* b_ff2=(const float*)d_in[19];
    const float* ln_out_g=(const float*)d_in[20];
    const float* ln_out_b=(const float*)d_in[21];
    const int* past_len=(const int*)d_in[22];
    float* dout=(float*)d_out_v;

    float *res,*ff2b_,*ff2c;
    bf16 *cath,*catl,*qh,*ql,*kh,*kl,*vh,*vl,*ah,*al;
    bf16 *ffinh,*ffinl,*ffhh,*ffhl;
    bf16 *wqh,*wql,*wkvh,*wkvl,*woh,*wol,*w1h,*w1l,*w2h,*w2l;
    cudaGetSymbolAddress((void**)&res,g_res);
    cudaGetSymbolAddress((void**)&ff2b_,g_ff2);
    cudaGetSymbolAddress((void**)&ff2c,g_ff2b);
    cudaGetSymbolAddress((void**)&cath,g_cat_h); cudaGetSymbolAddress((void**)&catl,g_cat_l);
    cudaGetSymbolAddress((void**)&qh,g_qh); cudaGetSymbolAddress((void**)&ql,g_ql);
    cudaGetSymbolAddress((void**)&kh,g_kh); cudaGetSymbolAddress((void**)&kl,g_kl);
    cudaGetSymbolAddress((void**)&vh,g_vh); cudaGetSymbolAddress((void**)&vl,g_vl);
    cudaGetSymbolAddress((void**)&ah,g_ah); cudaGetSymbolAddress((void**)&al,g_al);
    cudaGetSymbolAddress((void**)&ffinh,g_ffin_h); cudaGetSymbolAddress((void**)&ffinl,g_ffin_l);
    cudaGetSymbolAddress((void**)&ffhh,g_ffh_h); cudaGetSymbolAddress((void**)&ffhl,g_ffh_l);
    cudaGetSymbolAddress((void**)&wqh,g_wq_h); cudaGetSymbolAddress((void**)&wql,g_wq_l);
    cudaGetSymbolAddress((void**)&wkvh,g_wkv_h); cudaGetSymbolAddress((void**)&wkvl,g_wkv_l);
    cudaGetSymbolAddress((void**)&woh,g_wo_h); cudaGetSymbolAddress((void**)&wol,g_wo_l);
    cudaGetSymbolAddress((void**)&w1h,g_w1_h); cudaGetSymbolAddress((void**)&w1l,g_w1_l);
    cudaGetSymbolAddress((void**)&w2h,g_w2_h); cudaGetSymbolAddress((void**)&w2l,g_w2_l);

    cudaFuncSetAttribute(gemm_mma, cudaFuncAttributeMaxDynamicSharedMemorySize, GEMM_SMEM);
    cudaFuncSetAttribute(gemm_qkv, cudaFuncAttributeMaxDynamicSharedMemorySize, GEMM_SMEM);

    // one merged split launch: state_mems + all 5 weight tensors
    k_split_all<<<SPLITALL_BLOCKS,256>>>(
        state_mems, cath, catl,
        W_q, wqh, wql,
        W_kv, wkvh, wkvl,
        W_out, woh, wol,
        W_ff1, w1h, w1l,
        W_ff2, w2h, w2l);
    k_ln_in<<<TTm*BBm,256>>>(right_ctx, utterance, ln_in_g, ln_in_b);
    k_summary<<<BD/256,256>>>();
    // merged Q + KV projection
    gemm_qkv<<<QBLK+16*82,256,GEMM_SMEM>>>(cath, catl,
        wqh, wql, b_q, qh, ql,
        wkvh, wkvl, b_kv, kh, kl, vh, vl,
        dout+S4_OFF+(size_t)128*BD, dout+S5_OFF+(size_t)128*BD);
    // merged lc_key + lc_val split with mirror
    k_split_mir2<<<MIR2_BLOCKS,256>>>(lc_key, lc_val,
        kh+(size_t)36*BD, kl+(size_t)36*BD, vh+(size_t)36*BD, vl+(size_t)36*BD,
        dout+S4_OFF, dout+S5_OFF);
    // attention: qt-blocked QK^T, softmax, PV (R13 best)
    k_qk<<<dim3(3,1024),128>>>(past_len);
    k_softmax2<<<1024*192,128>>>();
    k_pv<<<dim3(3,1024),128>>>();
    // W_out projection with fused residual + clip (mode 3)
    gemm_mma<<<dim3(8,81),256,GEMM_SMEM>>>(ah, al, Dm, woh, wol, Dm,
        b_out, QQm*BBm, Dm, 3, res, nullptr, nullptr, Dm, nullptr, nullptr,
        (float*)right_ctx, (float*)utterance, dout+S2_OFF);
    // FFN
    k_ln_ff<<<TTm*BBm,256>>>(ln_ff_g, ln_ff_b);
    gemm_mma<<<dim3(32,80),256,GEMM_SMEM>>>(ffinh, ffinl, Dm, w1h, w1l, Dm,
        b_ff1, TTm*BBm, Dm, 1, nullptr, ffhh, ffhl, FFNm, nullptr, nullptr, nullptr, nullptr, nullptr);
    // FF2 split-K x2
    gemm_mma<<<dim3(8,80,2),256,GEMM_SMEM>>>(ffhh, ffhl, FFNm, w2h, w2l, FFNm,
        b_ff2, TTm*BBm, 2048, 0, ff2b_, nullptr, nullptr, Dm, nullptr, nullptr,
        nullptr, nullptr, ff2c);
    k_ln_final<<<TTm*BBm,256>>>(ln_out_g, ln_out_b, dout);
    // state-carry
    cudaMemcpyAsync(dout+S3_OFF, state_mems+BD, (size_t)3*BD*sizeof(float), cudaMemcpyDeviceToDevice, 0);
    cudaMemcpyAsync(dout+S3_OFF+(size_t)3*BD, mems_in, (size_t)BD*sizeof(float), cudaMemcpyDeviceToDevice, 0);
}